// round 13
// baseline (speedup 1.0000x reference)
#include <cuda_runtime.h>
#include <cuda_bf16.h>
#include <math.h>
#include <stdint.h>

#define Tn  2048
#define Dm  1024
#define FFm 4096
#define Vv  32000
#define Bm  2
#define Sm  1024
#define Hm  16
#define Lm  6

// ---------------- scratch (static device globals; no allocation) ------------
__device__ float g_x  [Tn * Dm];          // residual stream
__device__ float g_h  [Tn * Dm];          // rms output (fp32)
__device__ float g_q  [Tn * Dm];
__device__ float g_k  [Tn * Dm];
__device__ float g_v  [Tn * Dm];
__device__ float g_att[Tn * Dm];          // attention output (fp32)
__device__ float g_gate[(long)Tn * FFm];
__device__ float g_up  [(long)Tn * FFm];

// int8 activation quant buffers (+ per-64-chunk scales)
__device__ int8_t g_hq1[Tn * Dm],  g_hq2[Tn * Dm];
__device__ float  g_hd [Tn * (Dm / 64)];
__device__ int8_t g_aq1[Tn * Dm],  g_aq2[Tn * Dm];
__device__ float  g_ad [Tn * (Dm / 64)];
__device__ int8_t g_fq1[(long)Tn * FFm], g_fq2[(long)Tn * FFm];
__device__ float  g_fd [(long)Tn * (FFm / 64)];

// int8 ternary weight caches (exact)
__device__ int8_t g_wq[(long)Lm * Dm * Dm];
__device__ int8_t g_wk[(long)Lm * Dm * Dm];
__device__ int8_t g_wv[(long)Lm * Dm * Dm];
__device__ int8_t g_wo[(long)Lm * Dm * Dm];
__device__ int8_t g_wg[(long)Lm * FFm * Dm];
__device__ int8_t g_wu[(long)Lm * FFm * Dm];
__device__ int8_t g_wd[(long)Lm * FFm * Dm];
__device__ int8_t g_wh[(long)Vv * Dm];

__device__ __forceinline__ void cp_async16(uint32_t dst, const void* src) {
    asm volatile("cp.async.cg.shared.global [%0], [%1], 16;" :: "r"(dst), "l"(src));
}
__device__ __forceinline__ void cp_async4(uint32_t dst, const void* src) {
    asm volatile("cp.async.ca.shared.global [%0], [%1], 4;" :: "r"(dst), "l"(src));
}
__device__ __forceinline__ void cp_commit() {
    asm volatile("cp.async.commit_group;");
}
__device__ __forceinline__ uint32_t smem_u32(const void* p) {
    return (uint32_t)__cvta_generic_to_shared(p);
}
__device__ __forceinline__ void ldsm_x4(uint32_t* r, uint32_t addr) {
    asm volatile("ldmatrix.sync.aligned.m8n8.x4.shared.b16 {%0,%1,%2,%3}, [%4];"
                 : "=r"(r[0]), "=r"(r[1]), "=r"(r[2]), "=r"(r[3]) : "r"(addr));
}
__device__ __forceinline__ void mma_s8(int* d, const uint32_t* a,
                                       const uint32_t* b) {
    asm volatile(
        "mma.sync.aligned.m16n8k32.row.col.s32.s8.s8.s32 "
        "{%0,%1,%2,%3}, {%4,%5,%6,%7}, {%8,%9}, {%0,%1,%2,%3};"
        : "+r"(d[0]), "+r"(d[1]), "+r"(d[2]), "+r"(d[3])
        : "r"(a[0]), "r"(a[1]), "r"(a[2]), "r"(a[3]), "r"(b[0]), "r"(b[1]));
}

// ---------------- single-launch weight fp32 -> int8 --------------------------
struct WAll {
    const float* src[8];
    int8_t*      dst[8];
    long         cum[9];   // cumulative in 4-element units
};
__global__ void w2i8_all_kernel(WAll wa) {
    long i4 = (long)blockIdx.x * blockDim.x + threadIdx.x;
    if (i4 >= wa.cum[8]) return;
    int seg = 0;
    #pragma unroll
    for (int s = 0; s < 7; s++) if (i4 >= wa.cum[s + 1]) seg = s + 1;
    long li = (i4 - wa.cum[seg]) * 4;
    float4 v = *(const float4*)&wa.src[seg][li];
    char4 c = make_char4((signed char)v.x, (signed char)v.y,
                         (signed char)v.z, (signed char)v.w);
    *(char4*)&wa.dst[seg][li] = c;
}

// ---------------- per-64-chunk 2-level int8 quantization ---------------------
// x = d*q1 + (d/254)*q2 + eps, |eps| <= chunk_max * 1.6e-5
__global__ void quant_kernel(const float* __restrict__ X,
                             int8_t* __restrict__ Q1, int8_t* __restrict__ Q2,
                             float* __restrict__ D, long nCh) {
    long ch = (long)blockIdx.x * 8 + (threadIdx.x >> 5);
    if (ch >= nCh) return;
    int ln = threadIdx.x & 31;
    long base = ch * 64 + ln * 2;
    float2 x = *(const float2*)&X[base];
    float mx = fmaxf(fabsf(x.x), fabsf(x.y));
    #pragma unroll
    for (int o = 16; o > 0; o >>= 1)
        mx = fmaxf(mx, __shfl_xor_sync(0xffffffffu, mx, o));
    float invd = mx > 0.f ? 127.f / mx : 0.f;
    float d    = mx > 0.f ? mx * (1.f / 127.f) : 0.f;
    float q1a = fminf(fmaxf(rintf(x.x * invd), -127.f), 127.f);
    float q1b = fminf(fmaxf(rintf(x.y * invd), -127.f), 127.f);
    float ra = fmaf(-q1a, d, x.x);
    float rb = fmaf(-q1b, d, x.y);
    float q2a = fminf(fmaxf(rintf(ra * invd * 254.f), -127.f), 127.f);
    float q2b = fminf(fmaxf(rintf(rb * invd * 254.f), -127.f), 127.f);
    *(char2*)&Q1[base] = make_char2((signed char)q1a, (signed char)q1b);
    *(char2*)&Q2[base] = make_char2((signed char)q2a, (signed char)q2b);
    if (ln == 0) D[ch] = d;
}

// ---------------- embedding + positional ------------------------------------
__global__ void embed_kernel(const int* __restrict__ ids,
                             const float* __restrict__ et,
                             const float* __restrict__ es,
                             const float* __restrict__ pe,
                             float* __restrict__ x) {
    int t  = blockIdx.x;
    int id = ids[t];
    int s  = t % Sm;
    for (int d = threadIdx.x; d < Dm; d += blockDim.x) {
        long wi = (long)id * Dm + d;
        x[(long)t * Dm + d] = et[wi] * es[wi >> 7] + pe[s * Dm + d];
    }
}

// ---------------- RMSNorm (fp32 out) ------------------------------------------
__global__ void rms_kernel(const float* __restrict__ X,
                           const float* __restrict__ w,
                           float* __restrict__ Y) {
    int t = blockIdx.x, tid = threadIdx.x;
    __shared__ float red[256];
    float s = 0.f;
    for (int d = tid; d < Dm; d += 256) {
        float v = X[(long)t * Dm + d];
        s += v * v;
    }
    red[tid] = s; __syncthreads();
    for (int o = 128; o > 0; o >>= 1) {
        if (tid < o) red[tid] += red[tid + o];
        __syncthreads();
    }
    float r = rsqrtf(red[0] / Dm + 1e-6f);
    for (int d = tid; d < Dm; d += 256)
        Y[(long)t * Dm + d] = X[(long)t * Dm + d] * r * w[d];
}

// ---------------- int8 2-level GEMM, 128x128 tile -----------------------------
// Y[m,r] = (res?res:0) + sum_c delta[m,c]*sc[r,g(c)]*(S1[c] + S2[c]/254)
#define SAS8 80                        // 64 data bytes + 16 pad per row
#define TILE8 (128 * SAS8)
#define STAGE8 (3 * TILE8)             // q1, q2, W
#define MAXG 32
#define GEMM_SMEM (2 * STAGE8 + MAXG * 128 * (int)sizeof(float) \
                   + 2 * 128 * (int)sizeof(float))

__device__ __forceinline__ void gemm_core(const int8_t* __restrict__ Q1x,
                                          const int8_t* __restrict__ Q2x,
                                          const float* __restrict__ Dx,
                                          const int8_t* __restrict__ W8,
                                          const float* __restrict__ Sc,
                                          const float* __restrict__ res,
                                          float* __restrict__ Y,
                                          int R, int IN, int bm, int bn) {
    extern __shared__ char smp8[];
    char*  tiles = smp8;
    float* sSc = (float*)(smp8 + 2 * STAGE8);
    float* sD  = sSc + MAXG * 128;       // [2][128]

    const int tid  = threadIdx.x;
    const int warp = tid >> 5, lane = tid & 31;
    const int warpM = warp & 3, warpN = warp >> 2;
    const int groups = IN >> 7;
    const int nIter  = IN >> 6;
    const int lr = lane >> 2;
    const int lc = (lane & 3) << 1;
    const int lrow  = lane & 15;
    const int lcolB = (lane >> 4) << 4;   // byte col 0 / 16

    float master[2][4][4];
    #pragma unroll
    for (int a = 0; a < 2; a++)
        #pragma unroll
        for (int b = 0; b < 4; b++)
            #pragma unroll
            for (int c = 0; c < 4; c++) master[a][b][c] = 0.f;

    auto load_stage = [&](int st, int it) {
        char* q1 = tiles + st * STAGE8;
        char* q2 = q1 + TILE8;
        char* ws = q2 + TILE8;
        int row = tid >> 2, c16 = (tid & 3) << 4;   // 128 rows x 4 x 16B
        long gia = (long)(bm + row) * IN + (it << 6) + c16;
        cp_async16(smem_u32(q1 + row * SAS8 + c16), Q1x + gia);
        cp_async16(smem_u32(q2 + row * SAS8 + c16), Q2x + gia);
        cp_async16(smem_u32(ws + row * SAS8 + c16),
                   W8 + (long)(bn + row) * IN + (it << 6) + c16);
        if (tid < 128)
            cp_async4(smem_u32(sD + st * 128 + tid),
                      Dx + (long)(bm + tid) * nIter + it);
    };

    // stage 0 + all weight scales in commit group 0
    load_stage(0, 0);
    for (int idx = tid; idx < groups * 128; idx += 512) {
        int rl = idx & 127, g = idx >> 7;
        cp_async4(smem_u32(sSc + idx), Sc + (long)(bn + rl) * groups + g);
    }
    cp_commit();

    for (int it = 0; it < nIter; it++) {
        if (it + 1 < nIter) {
            load_stage((it + 1) & 1, it + 1);
            cp_commit();
            asm volatile("cp.async.wait_group 1;");
        } else {
            asm volatile("cp.async.wait_group 0;");
        }
        __syncthreads();

        const int st = it & 1;
        const char* q1 = tiles + st * STAGE8;
        const char* q2 = q1 + TILE8;
        const char* ws = q2 + TILE8;
        const int g = it >> 1;

        // B fragments (weights) — shared across both passes
        uint32_t fb[2][4][2];   // [ks][nt][2]
        #pragma unroll
        for (int ks = 0; ks < 2; ks++)
            #pragma unroll
            for (int np = 0; np < 2; np++) {
                uint32_t t4[4];
                ldsm_x4(t4, smem_u32(ws + (warpN * 32 + np * 16 + lrow) * SAS8
                                     + ks * 32 + lcolB));
                fb[ks][np * 2 + 0][0] = t4[0]; fb[ks][np * 2 + 0][1] = t4[2];
                fb[ks][np * 2 + 1][0] = t4[1]; fb[ks][np * 2 + 1][1] = t4[3];
            }

        #pragma unroll
        for (int pass = 0; pass < 2; pass++) {
            const char* qa = pass ? q2 : q1;
            int acc[2][4][4];
            #pragma unroll
            for (int a = 0; a < 2; a++)
                #pragma unroll
                for (int b = 0; b < 4; b++)
                    #pragma unroll
                    for (int c = 0; c < 4; c++) acc[a][b][c] = 0;

            #pragma unroll
            for (int ks = 0; ks < 2; ks++) {
                uint32_t fa[2][4];
                #pragma unroll
                for (int mt = 0; mt < 2; mt++)
                    ldsm_x4(fa[mt], smem_u32(qa + (warpM * 32 + mt * 16 + lrow) * SAS8
                                             + ks * 32 + lcolB));
                #pragma unroll
                for (int mt = 0; mt < 2; mt++)
                    #pragma unroll
                    for (int nt = 0; nt < 4; nt++)
                        mma_s8(acc[mt][nt], fa[mt], fb[ks][nt]);
            }

            const float ps = pass ? (1.f / 254.f) : 1.f;
            #pragma unroll
            for (int mt = 0; mt < 2; mt++) {
                float d0 = sD[st * 128 + warpM * 32 + mt * 16 + lr] * ps;
                float d1 = sD[st * 128 + warpM * 32 + mt * 16 + lr + 8] * ps;
                #pragma unroll
                for (int nt = 0; nt < 4; nt++) {
                    int rl = warpN * 32 + nt * 8 + lc;
                    float s0 = sSc[g * 128 + rl];
                    float s1 = sSc[g * 128 + rl + 1];
                    master[mt][nt][0] += d0 * s0 * (float)acc[mt][nt][0];
                    master[mt][nt][1] += d0 * s1 * (float)acc[mt][nt][1];
                    master[mt][nt][2] += d1 * s0 * (float)acc[mt][nt][2];
                    master[mt][nt][3] += d1 * s1 * (float)acc[mt][nt][3];
                }
            }
        }
        __syncthreads();
    }

    #pragma unroll
    for (int mt = 0; mt < 2; mt++) {
        int m0 = bm + warpM * 32 + mt * 16 + lr;
        #pragma unroll
        for (int nt = 0; nt < 4; nt++) {
            int r0 = bn + warpN * 32 + nt * 8 + lc;
            float2 v0 = make_float2(master[mt][nt][0], master[mt][nt][1]);
            float2 v1 = make_float2(master[mt][nt][2], master[mt][nt][3]);
            if (res) {
                float2 p0 = *(const float2*)&res[(long)m0 * R + r0];
                float2 p1 = *(const float2*)&res[(long)(m0 + 8) * R + r0];
                v0.x += p0.x; v0.y += p0.y;
                v1.x += p1.x; v1.y += p1.y;
            }
            *(float2*)&Y[(long)m0 * R + r0]       = v0;
            *(float2*)&Y[(long)(m0 + 8) * R + r0] = v1;
        }
    }
}

__global__ void __launch_bounds__(512)
gemm_kernel(const int8_t* __restrict__ Q1x, const int8_t* __restrict__ Q2x,
            const float* __restrict__ Dx, const int8_t* __restrict__ W8,
            const float* __restrict__ Sc, const float* __restrict__ res,
            float* __restrict__ Y, int R, int IN) {
    gemm_core(Q1x, Q2x, Dx, W8, Sc, res, Y, R, IN,
              blockIdx.y * 128, blockIdx.x * 128);
}

struct GB3 {
    const int8_t *w0, *w1, *w2;
    const float  *s0, *s1, *s2;
    float *y0, *y1, *y2;
};
__global__ void __launch_bounds__(512)
gemm_batch(const int8_t* __restrict__ Q1x, const int8_t* __restrict__ Q2x,
           const float* __restrict__ Dx, GB3 gb, int R, int IN) {
    int z = blockIdx.z;
    const int8_t* W  = (z == 0) ? gb.w0 : (z == 1) ? gb.w1 : gb.w2;
    const float*  Sc = (z == 0) ? gb.s0 : (z == 1) ? gb.s1 : gb.s2;
    float*        Y  = (z == 0) ? gb.y0 : (z == 1) ? gb.y1 : gb.y2;
    gemm_core(Q1x, Q2x, Dx, W, Sc, nullptr, Y, R, IN,
              blockIdx.y * 128, blockIdx.x * 128);
}

// ---------------- balanced flash attention (fp32 in/out) ---------------------
#define ATTN_SMEM (4 * 64 * 65 * (int)sizeof(float))

__global__ void __launch_bounds__(128)
attn_flash_kernel(const float* __restrict__ Q,
                  const float* __restrict__ K,
                  const float* __restrict__ V,
                  const float* __restrict__ Hn,
                  const float* __restrict__ alpha,
                  int layer,
                  float* __restrict__ O) {
    extern __shared__ float sm[];
    float* sQ = sm;
    float* sK = sm + 64 * 65;
    float* sV = sm + 2 * 64 * 65;
    float* sP = sm + 3 * 64 * 65;

    const int nQT = Sm / 64;
    const int h = blockIdx.y, b = blockIdx.z;
    const int tid = threadIdx.x, w = tid >> 5, ln = tid & 31;
    const int ry = ln >> 3, cx = ln & 7;
    const int row0 = w * 16 + ry * 4;
    const int hoff = h * 64;

    float4 kr[8], vr[8];

    #pragma unroll
    for (int pass = 0; pass < 2; pass++) {
        const int qt = (pass == 0) ? blockIdx.x : (nQT - 1 - blockIdx.x);
        const long tok0 = (long)b * Sm + qt * 64;

        __syncthreads();
        for (int i = tid; i < 64 * 16; i += 128) {
            int r = i >> 4, c4 = (i & 15) << 2;
            float4 v4 = *(const float4*)&Q[(tok0 + r) * Dm + hoff + c4];
            sQ[r * 65 + c4 + 0] = v4.x; sQ[r * 65 + c4 + 1] = v4.y;
            sQ[r * 65 + c4 + 2] = v4.z; sQ[r * 65 + c4 + 3] = v4.w;
        }

        float m[4], l[4], acc[4][8];
        #pragma unroll
        for (int r = 0; r < 4; r++) {
            m[r] = -1e30f; l[r] = 0.f;
            #pragma unroll
            for (int d = 0; d < 8; d++) acc[r][d] = 0.f;
        }

        const int nkt = qt + 1;
        {
            long kbase = (long)b * Sm;
            #pragma unroll
            for (int p = 0; p < 8; p++) {
                int i = tid + p * 128;
                int r = i >> 4, c4 = (i & 15) << 2;
                kr[p] = *(const float4*)&K[(kbase + r) * Dm + hoff + c4];
                vr[p] = *(const float4*)&V[(kbase + r) * Dm + hoff + c4];
            }
        }

        for (int kt = 0; kt < nkt; kt++) {
            __syncthreads();
            #pragma unroll
            for (int p = 0; p < 8; p++) {
                int i = tid + p * 128;
                int r = i >> 4, c4 = (i & 15) << 2;
                sK[r * 65 + c4 + 0] = kr[p].x; sK[r * 65 + c4 + 1] = kr[p].y;
                sK[r * 65 + c4 + 2] = kr[p].z; sK[r * 65 + c4 + 3] = kr[p].w;
                sV[r * 65 + c4 + 0] = vr[p].x; sV[r * 65 + c4 + 1] = vr[p].y;
                sV[r * 65 + c4 + 2] = vr[p].z; sV[r * 65 + c4 + 3] = vr[p].w;
            }
            __syncthreads();

            if (kt + 1 < nkt) {
                long kbase = (long)b * Sm + (kt + 1) * 64;
                #pragma unroll
                for (int p = 0; p < 8; p++) {
                    int i = tid + p * 128;
                    int r = i >> 4, c4 = (i & 15) << 2;
                    kr[p] = *(const float4*)&K[(kbase + r) * Dm + hoff + c4];
                    vr[p] = *(const float4*)&V[(kbase + r) * Dm + hoff + c4];
                }
            }

            float s[4][8];
            #pragma unroll
            for (int r = 0; r < 4; r++)
                #pragma unroll
                for (int c = 0; c < 8; c++) s[r][c] = 0.f;
            for (int d = 0; d < 64; d++) {
                float qv[4], kv[8];
                #pragma unroll
                for (int r = 0; r < 4; r++) qv[r] = sQ[(row0 + r) * 65 + d];
                #pragma unroll
                for (int c = 0; c < 8; c++) kv[c] = sK[(cx * 8 + c) * 65 + d];
                #pragma unroll
                for (int r = 0; r < 4; r++)
                    #pragma unroll
                    for (int c = 0; c < 8; c++)
                        s[r][c] = fmaf(qv[r], kv[c], s[r][c]);
            }
            const bool diag = (kt == qt);
            #pragma unroll
            for (int r = 0; r < 4; r++)
                #pragma unroll
                for (int c = 0; c < 8; c++) {
                    s[r][c] *= 0.125f;
                    if (diag && (cx * 8 + c > row0 + r)) s[r][c] = -1e30f;
                }

            #pragma unroll
            for (int r = 0; r < 4; r++) {
                float mn = s[r][0];
                #pragma unroll
                for (int c = 1; c < 8; c++) mn = fmaxf(mn, s[r][c]);
                #pragma unroll
                for (int o = 1; o < 8; o <<= 1)
                    mn = fmaxf(mn, __shfl_xor_sync(0xffffffffu, mn, o));
                mn = fmaxf(mn, m[r]);
                float fac = expf(m[r] - mn);
                m[r] = mn;
                float ls = 0.f;
                #pragma unroll
                for (int c = 0; c < 8; c++) {
                    float p = expf(s[r][c] - mn);
                    sP[(row0 + r) * 65 + cx * 8 + c] = p;
                    ls += p;
                }
                #pragma unroll
                for (int o = 1; o < 8; o <<= 1)
                    ls += __shfl_xor_sync(0xffffffffu, ls, o);
                l[r] = l[r] * fac + ls;
                #pragma unroll
                for (int d = 0; d < 8; d++) acc[r][d] *= fac;
            }
            __syncwarp();

            for (int j = 0; j < 64; j++) {
                float pv[4], vv[8];
                #pragma unroll
                for (int r = 0; r < 4; r++) pv[r] = sP[(row0 + r) * 65 + j];
                #pragma unroll
                for (int d = 0; d < 8; d++) vv[d] = sV[j * 65 + cx * 8 + d];
                #pragma unroll
                for (int r = 0; r < 4; r++)
                    #pragma unroll
                    for (int d = 0; d < 8; d++)
                        acc[r][d] = fmaf(pv[r], vv[d], acc[r][d]);
            }
            __syncwarp();
        }

        float a = alpha[layer * Hm + h];
        #pragma unroll
        for (int r = 0; r < 4; r++) {
            float inv = 1.f / l[r];
            long t = tok0 + row0 + r;
            #pragma unroll
            for (int d = 0; d < 8; d++) {
                long oi = t * Dm + hoff + cx * 8 + d;
                O[oi] = acc[r][d] * inv + a * Hn[oi];
            }
        }
    }
}

// ---------------- SiLU(gate) * up -> fp32 (in-place into gate) ---------------
__global__ void silu_mul_kernel(float* __restrict__ g,
                                const float* __restrict__ u, long n4) {
    long i = ((long)blockIdx.x * blockDim.x + threadIdx.x);
    if (i < n4) {
        long b = i * 4;
        float4 gv = *(const float4*)&g[b];
        float4 uv = *(const float4*)&u[b];
        gv.x = (gv.x / (1.f + expf(-gv.x))) * uv.x;
        gv.y = (gv.y / (1.f + expf(-gv.y))) * uv.y;
        gv.z = (gv.z / (1.f + expf(-gv.z))) * uv.z;
        gv.w = (gv.w / (1.f + expf(-gv.w))) * uv.w;
        *(float4*)&g[b] = gv;
    }
}

// =============================================================================
extern "C" void kernel_launch(void* const* d_in, const int* in_sizes, int n_in,
                              void* d_out, int out_size) {
    const int*   ids    = (const int*)  d_in[0];
    const float* emb_t  = (const float*)d_in[1];
    const float* emb_s  = (const float*)d_in[2];
    const float* pos    = (const float*)d_in[3];
    const float* q_t    = (const float*)d_in[4];
    const float* q_s    = (const float*)d_in[5];
    const float* k_t    = (const float*)d_in[6];
    const float* k_s    = (const float*)d_in[7];
    const float* v_t    = (const float*)d_in[8];
    const float* v_s    = (const float*)d_in[9];
    const float* o_t    = (const float*)d_in[10];
    const float* o_s    = (const float*)d_in[11];
    const float* gt     = (const float*)d_in[12];
    const float* gs     = (const float*)d_in[13];
    const float* ut     = (const float*)d_in[14];
    const float* us     = (const float*)d_in[15];
    const float* dt     = (const float*)d_in[16];
    const float* ds     = (const float*)d_in[17];
    const float* alpha  = (const float*)d_in[18];
    const float* na_w   = (const float*)d_in[19];
    const float* nm_w   = (const float*)d_in[20];
    const float* nf_w   = (const float*)d_in[21];
    const float* head_t = (const float*)d_in[22];
    const float* head_s = (const float*)d_in[23];

    float *x, *h, *q, *k, *v, *att, *gate, *up;
    int8_t *hq1, *hq2, *aq1, *aq2, *fq1, *fq2;
    float *hd, *ad, *fd;
    int8_t *wq, *wk, *wv, *wo, *wg, *wu, *wd, *wh;
    cudaGetSymbolAddress((void**)&x,    g_x);
    cudaGetSymbolAddress((void**)&h,    g_h);
    cudaGetSymbolAddress((void**)&q,    g_q);
    cudaGetSymbolAddress((void**)&k,    g_k);
    cudaGetSymbolAddress((void**)&v,    g_v);
    cudaGetSymbolAddress((void**)&att,  g_att);
    cudaGetSymbolAddress((void**)&gate, g_gate);
    cudaGetSymbolAddress((void**)&up,   g_up);
    cudaGetSymbolAddress((void**)&hq1,  g_hq1); cudaGetSymbolAddress((void**)&hq2, g_hq2);
    cudaGetSymbolAddress((void**)&hd,   g_hd);
    cudaGetSymbolAddress((void**)&aq1,  g_aq1); cudaGetSymbolAddress((void**)&aq2, g_aq2);
    cudaGetSymbolAddress((void**)&ad,   g_ad);
    cudaGetSymbolAddress((void**)&fq1,  g_fq1); cudaGetSymbolAddress((void**)&fq2, g_fq2);
    cudaGetSymbolAddress((void**)&fd,   g_fd);
    cudaGetSymbolAddress((void**)&wq,   g_wq);
    cudaGetSymbolAddress((void**)&wk,   g_wk);
    cudaGetSymbolAddress((void**)&wv,   g_wv);
    cudaGetSymbolAddress((void**)&wo,   g_wo);
    cudaGetSymbolAddress((void**)&wg,   g_wg);
    cudaGetSymbolAddress((void**)&wu,   g_wu);
    cudaGetSymbolAddress((void**)&wd,   g_wd);
    cudaGetSymbolAddress((void**)&wh,   g_wh);

    const long sQsz = (long)Dm * Dm / 128;
    const long sFsz = (long)Dm * FFm / 128;
    const long nD = (long)Lm * Dm * Dm;
    const long nF = (long)Lm * FFm * Dm;
    const long nH = (long)Vv * Dm;

    static bool attr_done = false;
    if (!attr_done) {
        cudaFuncSetAttribute(gemm_kernel,
                             cudaFuncAttributeMaxDynamicSharedMemorySize, GEMM_SMEM);
        cudaFuncSetAttribute(gemm_batch,
                             cudaFuncAttributeMaxDynamicSharedMemorySize, GEMM_SMEM);
        cudaFuncSetAttribute(attn_flash_kernel,
                             cudaFuncAttributeMaxDynamicSharedMemorySize, ATTN_SMEM);
        attr_done = true;
    }

    // ---- single-launch weight conversion (fp32 ternary -> int8) ----
    {
        WAll wa;
        const float* srcs[8] = {q_t, k_t, v_t, o_t, gt, ut, dt, head_t};
        int8_t* dsts[8]      = {wq,  wk,  wv,  wo,  wg, wu, wd, wh};
        long  szs[8]         = {nD,  nD,  nD,  nD,  nF, nF, nF, nH};
        long c = 0;
        wa.cum[0] = 0;
        for (int i = 0; i < 8; i++) {
            wa.src[i] = srcs[i]; wa.dst[i] = dsts[i];
            c += szs[i] / 4; wa.cum[i + 1] = c;
        }
        w2i8_all_kernel<<<(unsigned)((c + 255) / 256), 256>>>(wa);
    }

    embed_kernel<<<Tn, 256>>>(ids, emb_t, emb_s, pos, x);

    dim3 gD(Dm / 128,  Tn / 128);        // 128
    dim3 gQKV(Dm / 128, Tn / 128, 3);    // 384
    dim3 gGU(FFm / 128, Tn / 128, 2);    // 1024
    dim3 gVg(Vv / 128, Tn / 128);        // 4000
    dim3 ga(Sm / 128, Hm, Bm);           // 256 balanced blocks

    const long chD = (long)Tn * (Dm / 64);    // 32768 chunks
    const long chF = (long)Tn * (FFm / 64);   // 131072 chunks
    const unsigned qbD = (unsigned)((chD + 7) / 8);
    const unsigned qbF = (unsigned)((chF + 7) / 8);

    for (int l = 0; l < Lm; l++) {
        long oD = (long)l * Dm * Dm;
        long oF = (long)l * FFm * Dm;

        rms_kernel<<<Tn, 256>>>(x, na_w + l * Dm, h);
        quant_kernel<<<qbD, 256>>>(h, hq1, hq2, hd, chD);

        GB3 qkv;
        qkv.w0 = wq + oD; qkv.s0 = q_s + l * sQsz; qkv.y0 = q;
        qkv.w1 = wk + oD; qkv.s1 = k_s + l * sQsz; qkv.y1 = k;
        qkv.w2 = wv + oD; qkv.s2 = v_s + l * sQsz; qkv.y2 = v;
        gemm_batch<<<gQKV, 512, GEMM_SMEM>>>(hq1, hq2, hd, qkv, Dm, Dm);

        attn_flash_kernel<<<ga, 128, ATTN_SMEM>>>(q, k, v, h, alpha, l, att);
        quant_kernel<<<qbD, 256>>>(att, aq1, aq2, ad, chD);

        gemm_kernel<<<gD, 512, GEMM_SMEM>>>(aq1, aq2, ad, wo + oD,
                                            o_s + l * sQsz, x, x, Dm, Dm);

        rms_kernel<<<Tn, 256>>>(x, nm_w + l * Dm, h);
        quant_kernel<<<qbD, 256>>>(h, hq1, hq2, hd, chD);

        GB3 gu;
        gu.w0 = wg + oF; gu.s0 = gs + l * sFsz; gu.y0 = gate;
        gu.w1 = wu + oF; gu.s1 = us + l * sFsz; gu.y1 = up;
        gu.w2 = gu.w1;   gu.s2 = gu.s1;         gu.y2 = up;
        gemm_batch<<<gGU, 512, GEMM_SMEM>>>(hq1, hq2, hd, gu, FFm, Dm);

        long n4 = (long)Tn * FFm / 4;
        silu_mul_kernel<<<(unsigned)((n4 + 255) / 256), 256>>>(gate, up, n4);
        quant_kernel<<<qbF, 256>>>(gate, fq1, fq2, fd, chF);

        gemm_kernel<<<gD, 512, GEMM_SMEM>>>(fq1, fq2, fd, wd + oF,
                                            ds + l * sFsz, x, x, Dm, FFm);
    }

    rms_kernel<<<Tn, 256>>>(x, nf_w, h);
    quant_kernel<<<qbD, 256>>>(h, hq1, hq2, hd, chD);
    gemm_kernel<<<gVg, 512, GEMM_SMEM>>>(hq1, hq2, hd, wh, head_s, nullptr,
                                         (float*)d_out, Vv, Dm);
}

// round 14
// speedup vs baseline: 2.0322x; 2.0322x over previous
#include <cuda_runtime.h>
#include <cuda_bf16.h>
#include <math.h>
#include <stdint.h>

#define Tn  2048
#define Dm  1024
#define FFm 4096
#define Vv  32000
#define Bm  2
#define Sm  1024
#define Hm  16
#define Lm  6

typedef __nv_bfloat16 bf16;

// ---------------- scratch (static device globals; no allocation) ------------
__device__ float g_x  [Tn * Dm];
__device__ bf16  g_hh [Tn * Dm];
__device__ bf16  g_hl [Tn * Dm];
__device__ float g_q  [Tn * Dm];
__device__ float g_k  [Tn * Dm];
__device__ float g_v  [Tn * Dm];
__device__ bf16  g_ah [Tn * Dm];
__device__ bf16  g_al [Tn * Dm];
__device__ float g_gate[(long)Tn * FFm];
__device__ float g_up  [(long)Tn * FFm];
__device__ bf16  g_gh [(long)Tn * FFm];
__device__ bf16  g_gl [(long)Tn * FFm];

// bf16 ternary weight caches
__device__ bf16 g_wq[(long)Lm * Dm * Dm];
__device__ bf16 g_wk[(long)Lm * Dm * Dm];
__device__ bf16 g_wv[(long)Lm * Dm * Dm];
__device__ bf16 g_wo[(long)Lm * Dm * Dm];
__device__ bf16 g_wg[(long)Lm * FFm * Dm];
__device__ bf16 g_wu[(long)Lm * FFm * Dm];
__device__ bf16 g_wd[(long)Lm * FFm * Dm];
__device__ bf16 g_wh[(long)Vv * Dm];

__device__ __forceinline__ void split_bf16(float v, bf16& hi, bf16& lo) {
    hi = __float2bfloat16(v);
    lo = __float2bfloat16(v - __bfloat162float(hi));
}
__device__ __forceinline__ void cp_async16(uint32_t dst, const void* src) {
    asm volatile("cp.async.cg.shared.global [%0], [%1], 16;" :: "r"(dst), "l"(src));
}
__device__ __forceinline__ void cp_async4(uint32_t dst, const void* src) {
    asm volatile("cp.async.ca.shared.global [%0], [%1], 4;" :: "r"(dst), "l"(src));
}
__device__ __forceinline__ void cp_commit() {
    asm volatile("cp.async.commit_group;");
}
__device__ __forceinline__ uint32_t smem_u32(const void* p) {
    return (uint32_t)__cvta_generic_to_shared(p);
}
__device__ __forceinline__ void ldsm_x4(uint32_t* r, uint32_t addr) {
    asm volatile("ldmatrix.sync.aligned.m8n8.x4.shared.b16 {%0,%1,%2,%3}, [%4];"
                 : "=r"(r[0]), "=r"(r[1]), "=r"(r[2]), "=r"(r[3]) : "r"(addr));
}
__device__ __forceinline__ void mma_bf16(float* d, const uint32_t* a,
                                         const uint32_t* b) {
    asm volatile(
        "mma.sync.aligned.m16n8k16.row.col.f32.bf16.bf16.f32 "
        "{%0,%1,%2,%3}, {%4,%5,%6,%7}, {%8,%9}, {%0,%1,%2,%3};"
        : "+f"(d[0]), "+f"(d[1]), "+f"(d[2]), "+f"(d[3])
        : "r"(a[0]), "r"(a[1]), "r"(a[2]), "r"(a[3]), "r"(b[0]), "r"(b[1]));
}

// ---------------- single-launch weight fp32 -> bf16 --------------------------
struct WAll {
    const float* src[8];
    bf16*        dst[8];
    long         cum[9];
};
__global__ void w2b_all_kernel(WAll wa) {
    long i4 = (long)blockIdx.x * blockDim.x + threadIdx.x;
    if (i4 >= wa.cum[8]) return;
    int seg = 0;
    #pragma unroll
    for (int s = 0; s < 7; s++) if (i4 >= wa.cum[s + 1]) seg = s + 1;
    long li = (i4 - wa.cum[seg]) * 4;
    float4 v = *(const float4*)&wa.src[seg][li];
    bf16* d = wa.dst[seg];
    *(__nv_bfloat162*)&d[li]     = __floats2bfloat162_rn(v.x, v.y);
    *(__nv_bfloat162*)&d[li + 2] = __floats2bfloat162_rn(v.z, v.w);
}

// ---------------- embedding + positional ------------------------------------
__global__ void embed_kernel(const int* __restrict__ ids,
                             const float* __restrict__ et,
                             const float* __restrict__ es,
                             const float* __restrict__ pe,
                             float* __restrict__ x) {
    int t  = blockIdx.x;
    int id = ids[t];
    int s  = t % Sm;
    for (int d = threadIdx.x; d < Dm; d += blockDim.x) {
        long wi = (long)id * Dm + d;
        x[(long)t * Dm + d] = et[wi] * es[wi >> 7] + pe[s * Dm + d];
    }
}

// ---------------- RMSNorm -> hi/lo bf16 --------------------------------------
__global__ void rms_kernel(const float* __restrict__ X,
                           const float* __restrict__ w,
                           bf16* __restrict__ Yh, bf16* __restrict__ Yl) {
    int t = blockIdx.x, tid = threadIdx.x;
    __shared__ float red[256];
    float s = 0.f;
    for (int d = tid; d < Dm; d += 256) {
        float v = X[(long)t * Dm + d];
        s += v * v;
    }
    red[tid] = s; __syncthreads();
    for (int o = 128; o > 0; o >>= 1) {
        if (tid < o) red[tid] += red[tid + o];
        __syncthreads();
    }
    float r = rsqrtf(red[0] / Dm + 1e-6f);
    for (int d = tid; d < Dm; d += 256) {
        float v = X[(long)t * Dm + d] * r * w[d];
        bf16 hi, lo; split_bf16(v, hi, lo);
        Yh[(long)t * Dm + d] = hi;
        Yl[(long)t * Dm + d] = lo;
    }
}

// ---------------- 2-pass GEMM, 64x128 tile, 256 thr, 2 CTA/SM (R10) ----------
#define SAS 72
#define A_ELE (64 * SAS)
#define W_ELE (128 * SAS)
#define STAGE_E (2 * A_ELE + W_ELE)          // Ah, Al (64 rows), W (128 rows)
#define MAXG 32
#define GEMM_SMEM (2 * STAGE_E * (int)sizeof(bf16) + MAXG * 128 * (int)sizeof(float))

__device__ __forceinline__ void gemm_core(const bf16* __restrict__ Xh,
                                          const bf16* __restrict__ Xl,
                                          const bf16* __restrict__ W,
                                          const float* __restrict__ Sc,
                                          const float* __restrict__ res,
                                          float* __restrict__ Y,
                                          int R, int IN, int bm, int bn) {
    extern __shared__ bf16 smp[];
    float* sSc = (float*)(smp + 2 * STAGE_E);   // [groups][128]

    const int tid  = threadIdx.x;
    const int warp = tid >> 5, lane = tid & 31;
    const int warpM = warp & 1, warpN = warp >> 1;   // 2M x 4N warps
    const int groups = IN >> 7;
    const int lr = lane >> 2;
    const int lc = (lane & 3) << 1;
    const int lrow  = lane & 15;
    const int lcol8 = (lane >> 4) << 3;

    float master[2][4][4];
    float temp  [2][4][4];
    #pragma unroll
    for (int a = 0; a < 2; a++)
        #pragma unroll
        for (int b = 0; b < 4; b++)
            #pragma unroll
            for (int c = 0; c < 4; c++) { master[a][b][c] = 0.f; temp[a][b][c] = 0.f; }

    const int nIter = IN >> 6;

    auto load_stage = [&](int st, int it) {
        bf16* ah = smp + st * STAGE_E;
        bf16* al = ah + A_ELE;
        bf16* ws = al + A_ELE;
        int k0 = it << 6;
        #pragma unroll
        for (int p = 0; p < 2; p++) {
            int idx = tid + p * 256;          // 0..511 : 64 rows x 8 chunks
            int m = idx >> 3, c8 = (idx & 7) << 3;
            long gi = (long)(bm + m) * IN + k0 + c8;
            cp_async16(smem_u32(ah + m * SAS + c8), Xh + gi);
            cp_async16(smem_u32(al + m * SAS + c8), Xl + gi);
        }
        #pragma unroll
        for (int p = 0; p < 4; p++) {
            int idx = tid + p * 256;          // 0..1023 : 128 rows x 8 chunks
            int n = idx >> 3, c8 = (idx & 7) << 3;
            cp_async16(smem_u32(ws + n * SAS + c8), W + (long)(bn + n) * IN + k0 + c8);
        }
    };

    // stage 0 + all scales in commit group 0
    load_stage(0, 0);
    for (int idx = tid; idx < groups * 128; idx += 256) {
        int rl = idx & 127, g = idx >> 7;
        cp_async4(smem_u32(sSc + idx), Sc + (long)(bn + rl) * groups + g);
    }
    cp_commit();

    for (int it = 0; it < nIter; it++) {
        if (it + 1 < nIter) {
            load_stage((it + 1) & 1, it + 1);
            cp_commit();
            asm volatile("cp.async.wait_group 1;");
        } else {
            asm volatile("cp.async.wait_group 0;");
        }
        __syncthreads();

        const int st = it & 1;
        const bf16* ah = smp + st * STAGE_E;
        const bf16* al = ah + A_ELE;
        const bf16* ws = al + A_ELE;

        #pragma unroll
        for (int ks = 0; ks < 4; ks++) {
            const int kb = ks * 16;
            uint32_t fah[2][4], fal[2][4], fb[4][2];
            #pragma unroll
            for (int mt = 0; mt < 2; mt++) {
                int m0 = warpM * 32 + mt * 16;
                ldsm_x4(fah[mt], smem_u32(ah + (m0 + lrow) * SAS + kb + lcol8));
                ldsm_x4(fal[mt], smem_u32(al + (m0 + lrow) * SAS + kb + lcol8));
            }
            #pragma unroll
            for (int np = 0; np < 2; np++) {
                int n0 = warpN * 32 + np * 16;
                uint32_t q[4];
                ldsm_x4(q, smem_u32(ws + (n0 + lrow) * SAS + kb + lcol8));
                fb[np * 2][0] = q[0];     fb[np * 2][1] = q[2];
                fb[np * 2 + 1][0] = q[1]; fb[np * 2 + 1][1] = q[3];
            }
            #pragma unroll
            for (int mt = 0; mt < 2; mt++)
                #pragma unroll
                for (int nt = 0; nt < 4; nt++) {
                    mma_bf16(temp[mt][nt], fah[mt], fb[nt]);
                    mma_bf16(temp[mt][nt], fal[mt], fb[nt]);
                }
        }

        if (it & 1) {   // 128-K group boundary: fold with smem-cached scales
            int g = it >> 1;
            #pragma unroll
            for (int nt = 0; nt < 4; nt++) {
                int rl = warpN * 32 + nt * 8 + lc;
                float s0 = sSc[g * 128 + rl];
                float s1 = sSc[g * 128 + rl + 1];
                #pragma unroll
                for (int mt = 0; mt < 2; mt++) {
                    master[mt][nt][0] += s0 * temp[mt][nt][0];
                    master[mt][nt][1] += s1 * temp[mt][nt][1];
                    master[mt][nt][2] += s0 * temp[mt][nt][2];
                    master[mt][nt][3] += s1 * temp[mt][nt][3];
                    temp[mt][nt][0] = 0.f; temp[mt][nt][1] = 0.f;
                    temp[mt][nt][2] = 0.f; temp[mt][nt][3] = 0.f;
                }
            }
        }
        __syncthreads();
    }

    #pragma unroll
    for (int mt = 0; mt < 2; mt++) {
        int m0 = bm + warpM * 32 + mt * 16 + lr;
        #pragma unroll
        for (int nt = 0; nt < 4; nt++) {
            int r0 = bn + warpN * 32 + nt * 8 + lc;
            float2 v0 = make_float2(master[mt][nt][0], master[mt][nt][1]);
            float2 v1 = make_float2(master[mt][nt][2], master[mt][nt][3]);
            if (res) {
                float2 p0 = *(const float2*)&res[(long)m0 * R + r0];
                float2 p1 = *(const float2*)&res[(long)(m0 + 8) * R + r0];
                v0.x += p0.x; v0.y += p0.y;
                v1.x += p1.x; v1.y += p1.y;
            }
            *(float2*)&Y[(long)m0 * R + r0]       = v0;
            *(float2*)&Y[(long)(m0 + 8) * R + r0] = v1;
        }
    }
}

__global__ void __launch_bounds__(256, 2)
gemm_kernel(const bf16* __restrict__ Xh, const bf16* __restrict__ Xl,
            const bf16* __restrict__ W, const float* __restrict__ Sc,
            const float* __restrict__ res, float* __restrict__ Y,
            int R, int IN) {
    gemm_core(Xh, Xl, W, Sc, res, Y, R, IN, blockIdx.y * 64, blockIdx.x * 128);
}

struct GB3 {
    const bf16 *w0, *w1, *w2;
    const float *s0, *s1, *s2;
    float *y0, *y1, *y2;
};
__global__ void __launch_bounds__(256, 2)
gemm_batch(const bf16* __restrict__ Xh, const bf16* __restrict__ Xl,
           GB3 gb, int R, int IN) {
    int z = blockIdx.z;
    const bf16*  W  = (z == 0) ? gb.w0 : (z == 1) ? gb.w1 : gb.w2;
    const float* Sc = (z == 0) ? gb.s0 : (z == 1) ? gb.s1 : gb.s2;
    float*       Y  = (z == 0) ? gb.y0 : (z == 1) ? gb.y1 : gb.y2;
    gemm_core(Xh, Xl, W, Sc, nullptr, Y, R, IN, blockIdx.y * 64, blockIdx.x * 128);
}

// ---------------- balanced flash attention (R9: 128 thr, stride-65) ----------
#define ATTN_SMEM (4 * 64 * 65 * (int)sizeof(float))

__global__ void __launch_bounds__(128)
attn_flash_kernel(const float* __restrict__ Q,
                  const float* __restrict__ K,
                  const float* __restrict__ V,
                  const bf16* __restrict__ Hh,
                  const bf16* __restrict__ Hl,
                  const float* __restrict__ alpha,
                  int layer,
                  bf16* __restrict__ Oh, bf16* __restrict__ Ol) {
    extern __shared__ float sm[];
    float* sQ = sm;
    float* sK = sm + 64 * 65;
    float* sV = sm + 2 * 64 * 65;
    float* sP = sm + 3 * 64 * 65;

    const int nQT = Sm / 64;
    const int h = blockIdx.y, b = blockIdx.z;
    const int tid = threadIdx.x, w = tid >> 5, ln = tid & 31;
    const int ry = ln >> 3, cx = ln & 7;
    const int row0 = w * 16 + ry * 4;
    const int hoff = h * 64;

    #pragma unroll
    for (int pass = 0; pass < 2; pass++) {
        const int qt = (pass == 0) ? blockIdx.x : (nQT - 1 - blockIdx.x);
        const long tok0 = (long)b * Sm + qt * 64;

        __syncthreads();
        for (int i = tid; i < 64 * 16; i += 128) {
            int r = i >> 4, c4 = (i & 15) << 2;
            float4 v4 = *(const float4*)&Q[(tok0 + r) * Dm + hoff + c4];
            sQ[r * 65 + c4 + 0] = v4.x; sQ[r * 65 + c4 + 1] = v4.y;
            sQ[r * 65 + c4 + 2] = v4.z; sQ[r * 65 + c4 + 3] = v4.w;
        }

        float m[4], l[4], acc[4][8];
        #pragma unroll
        for (int r = 0; r < 4; r++) {
            m[r] = -1e30f; l[r] = 0.f;
            #pragma unroll
            for (int d = 0; d < 8; d++) acc[r][d] = 0.f;
        }

        const int nkt = qt + 1;
        for (int kt = 0; kt < nkt; kt++) {
            __syncthreads();
            long kbase = (long)b * Sm + kt * 64;
            for (int i = tid; i < 64 * 16; i += 128) {
                int r = i >> 4, c4 = (i & 15) << 2;
                float4 k4 = *(const float4*)&K[(kbase + r) * Dm + hoff + c4];
                sK[r * 65 + c4 + 0] = k4.x; sK[r * 65 + c4 + 1] = k4.y;
                sK[r * 65 + c4 + 2] = k4.z; sK[r * 65 + c4 + 3] = k4.w;
                float4 v4 = *(const float4*)&V[(kbase + r) * Dm + hoff + c4];
                sV[r * 65 + c4 + 0] = v4.x; sV[r * 65 + c4 + 1] = v4.y;
                sV[r * 65 + c4 + 2] = v4.z; sV[r * 65 + c4 + 3] = v4.w;
            }
            __syncthreads();

            float s[4][8];
            #pragma unroll
            for (int r = 0; r < 4; r++)
                #pragma unroll
                for (int c = 0; c < 8; c++) s[r][c] = 0.f;
            for (int d = 0; d < 64; d++) {
                float qv[4], kv[8];
                #pragma unroll
                for (int r = 0; r < 4; r++) qv[r] = sQ[(row0 + r) * 65 + d];
                #pragma unroll
                for (int c = 0; c < 8; c++) kv[c] = sK[(cx * 8 + c) * 65 + d];
                #pragma unroll
                for (int r = 0; r < 4; r++)
                    #pragma unroll
                    for (int c = 0; c < 8; c++)
                        s[r][c] = fmaf(qv[r], kv[c], s[r][c]);
            }
            const bool diag = (kt == qt);
            #pragma unroll
            for (int r = 0; r < 4; r++)
                #pragma unroll
                for (int c = 0; c < 8; c++) {
                    s[r][c] *= 0.125f;
                    if (diag && (cx * 8 + c > row0 + r)) s[r][c] = -1e30f;
                }

            #pragma unroll
            for (int r = 0; r < 4; r++) {
                float mn = s[r][0];
                #pragma unroll
                for (int c = 1; c < 8; c++) mn = fmaxf(mn, s[r][c]);
                #pragma unroll
                for (int o = 1; o < 8; o <<= 1)
                    mn = fmaxf(mn, __shfl_xor_sync(0xffffffffu, mn, o));
                mn = fmaxf(mn, m[r]);
                float fac = expf(m[r] - mn);
                m[r] = mn;
                float ls = 0.f;
                #pragma unroll
                for (int c = 0; c < 8; c++) {
                    float p = expf(s[r][c] - mn);
                    sP[(row0 + r) * 65 + cx * 8 + c] = p;
                    ls += p;
                }
                #pragma unroll
                for (int o = 1; o < 8; o <<= 1)
                    ls += __shfl_xor_sync(0xffffffffu, ls, o);
                l[r] = l[r] * fac + ls;
                #pragma unroll
                for (int d = 0; d < 8; d++) acc[r][d] *= fac;
            }
            __syncwarp();

            for (int j = 0; j < 64; j++) {
                float pv[4], vv[8];
                #pragma unroll
                for (int r = 0; r < 4; r++) pv[r] = sP[(row0 + r) * 65 + j];
                #pragma unroll
                for (int d = 0; d < 8; d++) vv[d] = sV[j * 65 + cx * 8 + d];
                #pragma unroll
                for (int r = 0; r < 4; r++)
                    #pragma unroll
                    for (int d = 0; d < 8; d++)
                        acc[r][d] = fmaf(pv[r], vv[d], acc[r][d]);
            }
            __syncwarp();
        }

        float a = alpha[layer * Hm + h];
        #pragma unroll
        for (int r = 0; r < 4; r++) {
            float inv = 1.f / l[r];
            long t = tok0 + row0 + r;
            #pragma unroll
            for (int d = 0; d < 8; d++) {
                long oi = t * Dm + hoff + cx * 8 + d;
                float hn = __bfloat162float(Hh[oi]) + __bfloat162float(Hl[oi]);
                float v = acc[r][d] * inv + a * hn;
                bf16 hi, lo; split_bf16(v, hi, lo);
                Oh[oi] = hi; Ol[oi] = lo;
            }
        }
    }
}

// ---------------- SiLU(gate) * up -> hi/lo bf16 (float4) ---------------------
__global__ void silu_mul_kernel(const float* __restrict__ g,
                                const float* __restrict__ u,
                                bf16* __restrict__ Yh, bf16* __restrict__ Yl,
                                long n4) {
    long i = ((long)blockIdx.x * blockDim.x + threadIdx.x);
    if (i < n4) {
        long b = i * 4;
        float4 gv = *(const float4*)&g[b];
        float4 uv = *(const float4*)&u[b];
        float v0 = (gv.x / (1.f + expf(-gv.x))) * uv.x;
        float v1 = (gv.y / (1.f + expf(-gv.y))) * uv.y;
        float v2 = (gv.z / (1.f + expf(-gv.z))) * uv.z;
        float v3 = (gv.w / (1.f + expf(-gv.w))) * uv.w;
        bf16 h0, l0, h1, l1, h2, l2, h3, l3;
        split_bf16(v0, h0, l0); split_bf16(v1, h1, l1);
        split_bf16(v2, h2, l2); split_bf16(v3, h3, l3);
        *(__nv_bfloat162*)&Yh[b]     = __nv_bfloat162(h0, h1);
        *(__nv_bfloat162*)&Yh[b + 2] = __nv_bfloat162(h2, h3);
        *(__nv_bfloat162*)&Yl[b]     = __nv_bfloat162(l0, l1);
        *(__nv_bfloat162*)&Yl[b + 2] = __nv_bfloat162(l2, l3);
    }
}

// =============================================================================
extern "C" void kernel_launch(void* const* d_in, const int* in_sizes, int n_in,
                              void* d_out, int out_size) {
    const int*   ids    = (const int*)  d_in[0];
    const float* emb_t  = (const float*)d_in[1];
    const float* emb_s  = (const float*)d_in[2];
    const float* pos    = (const float*)d_in[3];
    const float* q_t    = (const float*)d_in[4];
    const float* q_s    = (const float*)d_in[5];
    const float* k_t    = (const float*)d_in[6];
    const float* k_s    = (const float*)d_in[7];
    const float* v_t    = (const float*)d_in[8];
    const float* v_s    = (const float*)d_in[9];
    const float* o_t    = (const float*)d_in[10];
    const float* o_s    = (const float*)d_in[11];
    const float* gt     = (const float*)d_in[12];
    const float* gs     = (const float*)d_in[13];
    const float* ut     = (const float*)d_in[14];
    const float* us     = (const float*)d_in[15];
    const float* dt     = (const float*)d_in[16];
    const float* ds     = (const float*)d_in[17];
    const float* alpha  = (const float*)d_in[18];
    const float* na_w   = (const float*)d_in[19];
    const float* nm_w   = (const float*)d_in[20];
    const float* nf_w   = (const float*)d_in[21];
    const float* head_t = (const float*)d_in[22];
    const float* head_s = (const float*)d_in[23];

    float *x, *q, *k, *v, *gate, *up;
    bf16 *hh, *hl, *ah, *al, *gh, *gl;
    bf16 *wq, *wk, *wv, *wo, *wg, *wu, *wd, *wh;
    cudaGetSymbolAddress((void**)&x,    g_x);
    cudaGetSymbolAddress((void**)&hh,   g_hh);
    cudaGetSymbolAddress((void**)&hl,   g_hl);
    cudaGetSymbolAddress((void**)&q,    g_q);
    cudaGetSymbolAddress((void**)&k,    g_k);
    cudaGetSymbolAddress((void**)&v,    g_v);
    cudaGetSymbolAddress((void**)&ah,   g_ah);
    cudaGetSymbolAddress((void**)&al,   g_al);
    cudaGetSymbolAddress((void**)&gate, g_gate);
    cudaGetSymbolAddress((void**)&up,   g_up);
    cudaGetSymbolAddress((void**)&gh,   g_gh);
    cudaGetSymbolAddress((void**)&gl,   g_gl);
    cudaGetSymbolAddress((void**)&wq,   g_wq);
    cudaGetSymbolAddress((void**)&wk,   g_wk);
    cudaGetSymbolAddress((void**)&wv,   g_wv);
    cudaGetSymbolAddress((void**)&wo,   g_wo);
    cudaGetSymbolAddress((void**)&wg,   g_wg);
    cudaGetSymbolAddress((void**)&wu,   g_wu);
    cudaGetSymbolAddress((void**)&wd,   g_wd);
    cudaGetSymbolAddress((void**)&wh,   g_wh);

    const long sQsz = (long)Dm * Dm / 128;
    const long sFsz = (long)Dm * FFm / 128;
    const long nD = (long)Lm * Dm * Dm;
    const long nF = (long)Lm * FFm * Dm;
    const long nH = (long)Vv * Dm;

    static bool attr_done = false;
    if (!attr_done) {
        cudaFuncSetAttribute(gemm_kernel,
                             cudaFuncAttributeMaxDynamicSharedMemorySize, GEMM_SMEM);
        cudaFuncSetAttribute(gemm_batch,
                             cudaFuncAttributeMaxDynamicSharedMemorySize, GEMM_SMEM);
        cudaFuncSetAttribute(attn_flash_kernel,
                             cudaFuncAttributeMaxDynamicSharedMemorySize, ATTN_SMEM);
        attr_done = true;
    }

    // ---- single-launch weight conversion ----
    {
        WAll wa;
        const float* srcs[8] = {q_t, k_t, v_t, o_t, gt, ut, dt, head_t};
        bf16* dsts[8]        = {wq,  wk,  wv,  wo,  wg, wu, wd, wh};
        long  szs[8]         = {nD,  nD,  nD,  nD,  nF, nF, nF, nH};
        long c = 0;
        wa.cum[0] = 0;
        for (int i = 0; i < 8; i++) {
            wa.src[i] = srcs[i]; wa.dst[i] = dsts[i];
            c += szs[i] / 4; wa.cum[i + 1] = c;
        }
        w2b_all_kernel<<<(unsigned)((c + 255) / 256), 256>>>(wa);
    }

    embed_kernel<<<Tn, 256>>>(ids, emb_t, emb_s, pos, x);

    dim3 gD(Dm / 128,  Tn / 64);         // 8 x 32 = 256
    dim3 gQKV(Dm / 128, Tn / 64, 3);     // 768
    dim3 gGU(FFm / 128, Tn / 64, 2);     // 2048
    dim3 gVg(Vv / 128, Tn / 64);         // 8000
    dim3 ga(Sm / 128, Hm, Bm);           // 256 balanced blocks

    for (int l = 0; l < Lm; l++) {
        long oD = (long)l * Dm * Dm;
        long oF = (long)l * FFm * Dm;

        rms_kernel<<<Tn, 256>>>(x, na_w + l * Dm, hh, hl);

        GB3 qkv;
        qkv.w0 = wq + oD; qkv.s0 = q_s + l * sQsz; qkv.y0 = q;
        qkv.w1 = wk + oD; qkv.s1 = k_s + l * sQsz; qkv.y1 = k;
        qkv.w2 = wv + oD; qkv.s2 = v_s + l * sQsz; qkv.y2 = v;
        gemm_batch<<<gQKV, 256, GEMM_SMEM>>>(hh, hl, qkv, Dm, Dm);

        attn_flash_kernel<<<ga, 128, ATTN_SMEM>>>(q, k, v, hh, hl, alpha, l, ah, al);

        gemm_kernel<<<gD, 256, GEMM_SMEM>>>(ah, al, wo + oD, o_s + l * sQsz,
                                            x, x, Dm, Dm);

        rms_kernel<<<Tn, 256>>>(x, nm_w + l * Dm, hh, hl);

        GB3 gu;
        gu.w0 = wg + oF; gu.s0 = gs + l * sFsz; gu.y0 = gate;
        gu.w1 = wu + oF; gu.s1 = us + l * sFsz; gu.y1 = up;
        gu.w2 = gu.w1;   gu.s2 = gu.s1;         gu.y2 = up;
        gemm_batch<<<gGU, 256, GEMM_SMEM>>>(hh, hl, gu, FFm, Dm);

        long n4 = (long)Tn * FFm / 4;
        silu_mul_kernel<<<(unsigned)((n4 + 255) / 256), 256>>>(gate, up, gh, gl, n4);

        gemm_kernel<<<gD, 256, GEMM_SMEM>>>(gh, gl, wd + oF, ds + l * sFsz,
                                            x, x, Dm, FFm);
    }

    rms_kernel<<<Tn, 256>>>(x, nf_w, hh, hl);
    gemm_kernel<<<gVg, 256, GEMM_SMEM>>>(hh, hl, wh, head_s, nullptr,
                                         (float*)d_out, Vv, Dm);
}

// round 16
// speedup vs baseline: 2.0505x; 1.0090x over previous
#include <cuda_runtime.h>
#include <cuda_bf16.h>
#include <math.h>
#include <stdint.h>

#define Tn  2048
#define Dm  1024
#define FFm 4096
#define Vv  32000
#define Bm  2
#define Sm  1024
#define Hm  16
#define Lm  6

typedef __nv_bfloat16 bf16;

// ---------------- scratch (static device globals; no allocation) ------------
__device__ float g_x  [Tn * Dm];
__device__ bf16  g_hh [Tn * Dm];
__device__ bf16  g_hl [Tn * Dm];
__device__ float g_q  [Tn * Dm];
__device__ float g_k  [Tn * Dm];
__device__ float g_v  [Tn * Dm];
__device__ bf16  g_ah [Tn * Dm];
__device__ bf16  g_al [Tn * Dm];
__device__ float g_gate[(long)Tn * FFm];
__device__ float g_up  [(long)Tn * FFm];
__device__ bf16  g_gh [(long)Tn * FFm];
__device__ bf16  g_gl [(long)Tn * FFm];

// bf16 ternary weight caches
__device__ bf16 g_wq[(long)Lm * Dm * Dm];
__device__ bf16 g_wk[(long)Lm * Dm * Dm];
__device__ bf16 g_wv[(long)Lm * Dm * Dm];
__device__ bf16 g_wo[(long)Lm * Dm * Dm];
__device__ bf16 g_wg[(long)Lm * FFm * Dm];
__device__ bf16 g_wu[(long)Lm * FFm * Dm];
__device__ bf16 g_wd[(long)Lm * FFm * Dm];
__device__ bf16 g_wh[(long)Vv * Dm];

__device__ __forceinline__ void split_bf16(float v, bf16& hi, bf16& lo) {
    hi = __float2bfloat16(v);
    lo = __float2bfloat16(v - __bfloat162float(hi));
}
__device__ __forceinline__ void cp_async16(uint32_t dst, const void* src) {
    asm volatile("cp.async.cg.shared.global [%0], [%1], 16;" :: "r"(dst), "l"(src));
}
__device__ __forceinline__ void cp_async4(uint32_t dst, const void* src) {
    asm volatile("cp.async.ca.shared.global [%0], [%1], 4;" :: "r"(dst), "l"(src));
}
__device__ __forceinline__ void cp_commit() {
    asm volatile("cp.async.commit_group;");
}
__device__ __forceinline__ uint32_t smem_u32(const void* p) {
    return (uint32_t)__cvta_generic_to_shared(p);
}
__device__ __forceinline__ void ldsm_x4(uint32_t* r, uint32_t addr) {
    asm volatile("ldmatrix.sync.aligned.m8n8.x4.shared.b16 {%0,%1,%2,%3}, [%4];"
                 : "=r"(r[0]), "=r"(r[1]), "=r"(r[2]), "=r"(r[3]) : "r"(addr));
}
__device__ __forceinline__ void mma_bf16(float* d, const uint32_t* a,
                                         const uint32_t* b) {
    asm volatile(
        "mma.sync.aligned.m16n8k16.row.col.f32.bf16.bf16.f32 "
        "{%0,%1,%2,%3}, {%4,%5,%6,%7}, {%8,%9}, {%0,%1,%2,%3};"
        : "+f"(d[0]), "+f"(d[1]), "+f"(d[2]), "+f"(d[3])
        : "r"(a[0]), "r"(a[1]), "r"(a[2]), "r"(a[3]), "r"(b[0]), "r"(b[1]));
}

// ---------------- single-launch weight fp32 -> bf16 --------------------------
struct WAll {
    const float* src[8];
    bf16*        dst[8];
    long         cum[9];
};
__global__ void w2b_all_kernel(WAll wa) {
    long i4 = (long)blockIdx.x * blockDim.x + threadIdx.x;
    if (i4 >= wa.cum[8]) return;
    int seg = 0;
    #pragma unroll
    for (int s = 0; s < 7; s++) if (i4 >= wa.cum[s + 1]) seg = s + 1;
    long li = (i4 - wa.cum[seg]) * 4;
    float4 v = *(const float4*)&wa.src[seg][li];
    bf16* d = wa.dst[seg];
    *(__nv_bfloat162*)&d[li]     = __floats2bfloat162_rn(v.x, v.y);
    *(__nv_bfloat162*)&d[li + 2] = __floats2bfloat162_rn(v.z, v.w);
}

// ---------------- embedding + positional ------------------------------------
__global__ void embed_kernel(const int* __restrict__ ids,
                             const float* __restrict__ et,
                             const float* __restrict__ es,
                             const float* __restrict__ pe,
                             float* __restrict__ x) {
    int t  = blockIdx.x;
    int id = ids[t];
    int s  = t % Sm;
    for (int d = threadIdx.x; d < Dm; d += blockDim.x) {
        long wi = (long)id * Dm + d;
        x[(long)t * Dm + d] = et[wi] * es[wi >> 7] + pe[s * Dm + d];
    }
}

// ---------------- RMSNorm -> hi/lo bf16 (register-cached, float4) ------------
__global__ void rms_kernel(const float* __restrict__ X,
                           const float* __restrict__ w,
                           bf16* __restrict__ Yh, bf16* __restrict__ Yl) {
    int t = blockIdx.x, tid = threadIdx.x;
    __shared__ float red[256];
    long base = (long)t * Dm + tid * 4;
    float4 v4 = *(const float4*)&X[base];
    float s = v4.x * v4.x + v4.y * v4.y + v4.z * v4.z + v4.w * v4.w;
    red[tid] = s; __syncthreads();
    for (int o = 128; o > 0; o >>= 1) {
        if (tid < o) red[tid] += red[tid + o];
        __syncthreads();
    }
    float r = rsqrtf(red[0] / Dm + 1e-6f);
    float4 w4 = *(const float4*)&w[tid * 4];
    float y0 = v4.x * r * w4.x, y1 = v4.y * r * w4.y;
    float y2 = v4.z * r * w4.z, y3 = v4.w * r * w4.w;
    bf16 h0, l0, h1, l1, h2, l2, h3, l3;
    split_bf16(y0, h0, l0); split_bf16(y1, h1, l1);
    split_bf16(y2, h2, l2); split_bf16(y3, h3, l3);
    *(__nv_bfloat162*)&Yh[base]     = __nv_bfloat162(h0, h1);
    *(__nv_bfloat162*)&Yh[base + 2] = __nv_bfloat162(h2, h3);
    *(__nv_bfloat162*)&Yl[base]     = __nv_bfloat162(l0, l1);
    *(__nv_bfloat162*)&Yl[base + 2] = __nv_bfloat162(l2, l3);
}

// ---------------- 2-pass GEMM, 64x128 tile, 256 thr, 2 CTA/SM ----------------
#define SAS 72
#define A_ELE (64 * SAS)
#define W_ELE (128 * SAS)
#define STAGE_E (2 * A_ELE + W_ELE)
#define MAXG 32
#define GEMM_SMEM (2 * STAGE_E * (int)sizeof(bf16) + MAXG * 128 * (int)sizeof(float))

__device__ __forceinline__ void gemm_core(const bf16* __restrict__ Xh,
                                          const bf16* __restrict__ Xl,
                                          const bf16* __restrict__ W,
                                          const float* __restrict__ Sc,
                                          const float* __restrict__ res,
                                          float* __restrict__ Y,
                                          int R, int IN, int bm, int bn) {
    extern __shared__ bf16 smp[];
    float* sSc = (float*)(smp + 2 * STAGE_E);

    const int tid  = threadIdx.x;
    const int warp = tid >> 5, lane = tid & 31;
    const int warpM = warp & 1, warpN = warp >> 1;
    const int groups = IN >> 7;
    const int lr = lane >> 2;
    const int lc = (lane & 3) << 1;
    const int lrow  = lane & 15;
    const int lcol8 = (lane >> 4) << 3;

    float master[2][4][4];
    float temp  [2][4][4];
    #pragma unroll
    for (int a = 0; a < 2; a++)
        #pragma unroll
        for (int b = 0; b < 4; b++)
            #pragma unroll
            for (int c = 0; c < 4; c++) { master[a][b][c] = 0.f; temp[a][b][c] = 0.f; }

    const int nIter = IN >> 6;

    auto load_stage = [&](int st, int it) {
        bf16* ah = smp + st * STAGE_E;
        bf16* al = ah + A_ELE;
        bf16* ws = al + A_ELE;
        int k0 = it << 6;
        #pragma unroll
        for (int p = 0; p < 2; p++) {
            int idx = tid + p * 256;
            int m = idx >> 3, c8 = (idx & 7) << 3;
            long gi = (long)(bm + m) * IN + k0 + c8;
            cp_async16(smem_u32(ah + m * SAS + c8), Xh + gi);
            cp_async16(smem_u32(al + m * SAS + c8), Xl + gi);
        }
        #pragma unroll
        for (int p = 0; p < 4; p++) {
            int idx = tid + p * 256;
            int n = idx >> 3, c8 = (idx & 7) << 3;
            cp_async16(smem_u32(ws + n * SAS + c8), W + (long)(bn + n) * IN + k0 + c8);
        }
    };

    load_stage(0, 0);
    for (int idx = tid; idx < groups * 128; idx += 256) {
        int rl = idx & 127, g = idx >> 7;
        cp_async4(smem_u32(sSc + idx), Sc + (long)(bn + rl) * groups + g);
    }
    cp_commit();

    for (int it = 0; it < nIter; it++) {
        if (it + 1 < nIter) {
            load_stage((it + 1) & 1, it + 1);
            cp_commit();
            asm volatile("cp.async.wait_group 1;");
        } else {
            asm volatile("cp.async.wait_group 0;");
        }
        __syncthreads();

        const int st = it & 1;
        const bf16* ah = smp + st * STAGE_E;
        const bf16* al = ah + A_ELE;
        const bf16* ws = al + A_ELE;

        #pragma unroll
        for (int ks = 0; ks < 4; ks++) {
            const int kb = ks * 16;
            uint32_t fah[2][4], fal[2][4], fb[4][2];
            #pragma unroll
            for (int mt = 0; mt < 2; mt++) {
                int m0 = warpM * 32 + mt * 16;
                ldsm_x4(fah[mt], smem_u32(ah + (m0 + lrow) * SAS + kb + lcol8));
                ldsm_x4(fal[mt], smem_u32(al + (m0 + lrow) * SAS + kb + lcol8));
            }
            #pragma unroll
            for (int np = 0; np < 2; np++) {
                int n0 = warpN * 32 + np * 16;
                uint32_t q[4];
                ldsm_x4(q, smem_u32(ws + (n0 + lrow) * SAS + kb + lcol8));
                fb[np * 2][0] = q[0];     fb[np * 2][1] = q[2];
                fb[np * 2 + 1][0] = q[1]; fb[np * 2 + 1][1] = q[3];
            }
            #pragma unroll
            for (int mt = 0; mt < 2; mt++)
                #pragma unroll
                for (int nt = 0; nt < 4; nt++) {
                    mma_bf16(temp[mt][nt], fah[mt], fb[nt]);
                    mma_bf16(temp[mt][nt], fal[mt], fb[nt]);
                }
        }

        if (it & 1) {
            int g = it >> 1;
            #pragma unroll
            for (int nt = 0; nt < 4; nt++) {
                int rl = warpN * 32 + nt * 8 + lc;
                float s0 = sSc[g * 128 + rl];
                float s1 = sSc[g * 128 + rl + 1];
                #pragma unroll
                for (int mt = 0; mt < 2; mt++) {
                    master[mt][nt][0] += s0 * temp[mt][nt][0];
                    master[mt][nt][1] += s1 * temp[mt][nt][1];
                    master[mt][nt][2] += s0 * temp[mt][nt][2];
                    master[mt][nt][3] += s1 * temp[mt][nt][3];
                    temp[mt][nt][0] = 0.f; temp[mt][nt][1] = 0.f;
                    temp[mt][nt][2] = 0.f; temp[mt][nt][3] = 0.f;
                }
            }
        }
        __syncthreads();
    }

    #pragma unroll
    for (int mt = 0; mt < 2; mt++) {
        int m0 = bm + warpM * 32 + mt * 16 + lr;
        #pragma unroll
        for (int nt = 0; nt < 4; nt++) {
            int r0 = bn + warpN * 32 + nt * 8 + lc;
            float2 v0 = make_float2(master[mt][nt][0], master[mt][nt][1]);
            float2 v1 = make_float2(master[mt][nt][2], master[mt][nt][3]);
            if (res) {
                float2 p0 = *(const float2*)&res[(long)m0 * R + r0];
                float2 p1 = *(const float2*)&res[(long)(m0 + 8) * R + r0];
                v0.x += p0.x; v0.y += p0.y;
                v1.x += p1.x; v1.y += p1.y;
            }
            *(float2*)&Y[(long)m0 * R + r0]       = v0;
            *(float2*)&Y[(long)(m0 + 8) * R + r0] = v1;
        }
    }
}

__global__ void __launch_bounds__(256, 2)
gemm_kernel(const bf16* __restrict__ Xh, const bf16* __restrict__ Xl,
            const bf16* __restrict__ W, const float* __restrict__ Sc,
            const float* __restrict__ res, float* __restrict__ Y,
            int R, int IN) {
    gemm_core(Xh, Xl, W, Sc, res, Y, R, IN, blockIdx.y * 64, blockIdx.x * 128);
}

struct GB3 {
    const bf16 *w0, *w1, *w2;
    const float *s0, *s1, *s2;
    float *y0, *y1, *y2;
};
__global__ void __launch_bounds__(256, 2)
gemm_batch(const bf16* __restrict__ Xh, const bf16* __restrict__ Xl,
           GB3 gb, int R, int IN) {
    int z = blockIdx.z;
    const bf16*  W  = (z == 0) ? gb.w0 : (z == 1) ? gb.w1 : gb.w2;
    const float* Sc = (z == 0) ? gb.s0 : (z == 1) ? gb.s1 : gb.s2;
    float*       Y  = (z == 0) ? gb.y0 : (z == 1) ? gb.y1 : gb.y2;
    gemm_core(Xh, Xl, W, Sc, nullptr, Y, R, IN, blockIdx.y * 64, blockIdx.x * 128);
}

// ---------------- balanced flash attention (R14: 128 thr, stride-65) ---------
#define ATTN_SMEM (4 * 64 * 65 * (int)sizeof(float))

__global__ void __launch_bounds__(128)
attn_flash_kernel(const float* __restrict__ Q,
                  const float* __restrict__ K,
                  const float* __restrict__ V,
                  const bf16* __restrict__ Hh,
                  const bf16* __restrict__ Hl,
                  const float* __restrict__ alpha,
                  int layer,
                  bf16* __restrict__ Oh, bf16* __restrict__ Ol) {
    extern __shared__ float sm[];
    float* sQ = sm;
    float* sK = sm + 64 * 65;
    float* sV = sm + 2 * 64 * 65;
    float* sP = sm + 3 * 64 * 65;

    const int nQT = Sm / 64;
    const int h = blockIdx.y, b = blockIdx.z;
    const int tid = threadIdx.x, w = tid >> 5, ln = tid & 31;
    const int ry = ln >> 3, cx = ln & 7;
    const int row0 = w * 16 + ry * 4;
    const int hoff = h * 64;

    #pragma unroll
    for (int pass = 0; pass < 2; pass++) {
        const int qt = (pass == 0) ? blockIdx.x : (nQT - 1 - blockIdx.x);
        const long tok0 = (long)b * Sm + qt * 64;

        __syncthreads();
        for (int i = tid; i < 64 * 16; i += 128) {
            int r = i >> 4, c4 = (i & 15) << 2;
            float4 v4 = *(const float4*)&Q[(tok0 + r) * Dm + hoff + c4];
            sQ[r * 65 + c4 + 0] = v4.x; sQ[r * 65 + c4 + 1] = v4.y;
            sQ[r * 65 + c4 + 2] = v4.z; sQ[r * 65 + c4 + 3] = v4.w;
        }

        float m[4], l[4], acc[4][8];
        #pragma unroll
        for (int r = 0; r < 4; r++) {
            m[r] = -1e30f; l[r] = 0.f;
            #pragma unroll
            for (int d = 0; d < 8; d++) acc[r][d] = 0.f;
        }

        const int nkt = qt + 1;
        for (int kt = 0; kt < nkt; kt++) {
            __syncthreads();
            long kbase = (long)b * Sm + kt * 64;
            for (int i = tid; i < 64 * 16; i += 128) {
                int r = i >> 4, c4 = (i & 15) << 2;
                float4 k4 = *(const float4*)&K[(kbase + r) * Dm + hoff + c4];
                sK[r * 65 + c4 + 0] = k4.x; sK[r * 65 + c4 + 1] = k4.y;
                sK[r * 65 + c4 + 2] = k4.z; sK[r * 65 + c4 + 3] = k4.w;
                float4 v4 = *(const float4*)&V[(kbase + r) * Dm + hoff + c4];
                sV[r * 65 + c4 + 0] = v4.x; sV[r * 65 + c4 + 1] = v4.y;
                sV[r * 65 + c4 + 2] = v4.z; sV[r * 65 + c4 + 3] = v4.w;
            }
            __syncthreads();

            float s[4][8];
            #pragma unroll
            for (int r = 0; r < 4; r++)
                #pragma unroll
                for (int c = 0; c < 8; c++) s[r][c] = 0.f;
            for (int d = 0; d < 64; d++) {
                float qv[4], kv[8];
                #pragma unroll
                for (int r = 0; r < 4; r++) qv[r] = sQ[(row0 + r) * 65 + d];
                #pragma unroll
                for (int c = 0; c < 8; c++) kv[c] = sK[(cx * 8 + c) * 65 + d];
                #pragma unroll
                for (int r = 0; r < 4; r++)
                    #pragma unroll
                    for (int c = 0; c < 8; c++)
                        s[r][c] = fmaf(qv[r], kv[c], s[r][c]);
            }
            const bool diag = (kt == qt);
            #pragma unroll
            for (int r = 0; r < 4; r++)
                #pragma unroll
                for (int c = 0; c < 8; c++) {
                    s[r][c] *= 0.125f;
                    if (diag && (cx * 8 + c > row0 + r)) s[r][c] = -1e30f;
                }

            #pragma unroll
            for (int r = 0; r < 4; r++) {
                float mn = s[r][0];
                #pragma unroll
                for (int c = 1; c < 8; c++) mn = fmaxf(mn, s[r][c]);
                #pragma unroll
                for (int o = 1; o < 8; o <<= 1)
                    mn = fmaxf(mn, __shfl_xor_sync(0xffffffffu, mn, o));
                mn = fmaxf(mn, m[r]);
                float fac = __expf(m[r] - mn);
                m[r] = mn;
                float ls = 0.f;
                #pragma unroll
                for (int c = 0; c < 8; c++) {
                    float p = __expf(s[r][c] - mn);
                    sP[(row0 + r) * 65 + cx * 8 + c] = p;
                    ls += p;
                }
                #pragma unroll
                for (int o = 1; o < 8; o <<= 1)
                    ls += __shfl_xor_sync(0xffffffffu, ls, o);
                l[r] = l[r] * fac + ls;
                #pragma unroll
                for (int d = 0; d < 8; d++) acc[r][d] *= fac;
            }
            __syncwarp();

            for (int j = 0; j < 64; j++) {
                float pv[4], vv[8];
                #pragma unroll
                for (int r = 0; r < 4; r++) pv[r] = sP[(row0 + r) * 65 + j];
                #pragma unroll
                for (int d = 0; d < 8; d++) vv[d] = sV[j * 65 + cx * 8 + d];
                #pragma unroll
                for (int r = 0; r < 4; r++)
                    #pragma unroll
                    for (int d = 0; d < 8; d++)
                        acc[r][d] = fmaf(pv[r], vv[d], acc[r][d]);
            }
            __syncwarp();
        }

        float a = alpha[layer * Hm + h];
        #pragma unroll
        for (int r = 0; r < 4; r++) {
            float inv = 1.f / l[r];
            long t = tok0 + row0 + r;
            #pragma unroll
            for (int d = 0; d < 8; d++) {
                long oi = t * Dm + hoff + cx * 8 + d;
                float hn = __bfloat162float(Hh[oi]) + __bfloat162float(Hl[oi]);
                float v = acc[r][d] * inv + a * hn;
                bf16 hi, lo; split_bf16(v, hi, lo);
                Oh[oi] = hi; Ol[oi] = lo;
            }
        }
    }
}

// ---------------- SiLU(gate) * up -> hi/lo bf16 (float4, __expf) -------------
__global__ void silu_mul_kernel(const float* __restrict__ g,
                                const float* __restrict__ u,
                                bf16* __restrict__ Yh, bf16* __restrict__ Yl,
                                long n4) {
    long i = ((long)blockIdx.x * blockDim.x + threadIdx.x);
    if (i < n4) {
        long b = i * 4;
        float4 gv = *(const float4*)&g[b];
        float4 uv = *(const float4*)&u[b];
        float v0 = (gv.x / (1.f + __expf(-gv.x))) * uv.x;
        float v1 = (gv.y / (1.f + __expf(-gv.y))) * uv.y;
        float v2 = (gv.z / (1.f + __expf(-gv.z))) * uv.z;
        float v3 = (gv.w / (1.f + __expf(-gv.w))) * uv.w;
        bf16 h0, l0, h1, l1, h2, l2, h3, l3;
        split_bf16(v0, h0, l0); split_bf16(v1, h1, l1);
        split_bf16(v2, h2, l2); split_bf16(v3, h3, l3);
        *(__nv_bfloat162*)&Yh[b]     = __nv_bfloat162(h0, h1);
        *(__nv_bfloat162*)&Yh[b + 2] = __nv_bfloat162(h2, h3);
        *(__nv_bfloat162*)&Yl[b]     = __nv_bfloat162(l0, l1);
        *(__nv_bfloat162*)&Yl[b + 2] = __nv_bfloat162(l2, l3);
    }
}

// =============================================================================
extern "C" void kernel_launch(void* const* d_in, const int* in_sizes, int n_in,
                              void* d_out, int out_size) {
    const int*   ids    = (const int*)  d_in[0];
    const float* emb_t  = (const float*)d_in[1];
    const float* emb_s  = (const float*)d_in[2];
    const float* pos    = (const float*)d_in[3];
    const float* q_t    = (const float*)d_in[4];
    const float* q_s    = (const float*)d_in[5];
    const float* k_t    = (const float*)d_in[6];
    const float* k_s    = (const float*)d_in[7];
    const float* v_t    = (const float*)d_in[8];
    const float* v_s    = (const float*)d_in[9];
    const float* o_t    = (const float*)d_in[10];
    const float* o_s    = (const float*)d_in[11];
    const float* gt     = (const float*)d_in[12];
    const float* gs     = (const float*)d_in[13];
    const float* ut     = (const float*)d_in[14];
    const float* us     = (const float*)d_in[15];
    const float* dt     = (const float*)d_in[16];
    const float* ds     = (const float*)d_in[17];
    const float* alpha  = (const float*)d_in[18];
    const float* na_w   = (const float*)d_in[19];
    const float* nm_w   = (const float*)d_in[20];
    const float* nf_w   = (const float*)d_in[21];
    const float* head_t = (const float*)d_in[22];
    const float* head_s = (const float*)d_in[23];

    float *x, *q, *k, *v, *gate, *up;
    bf16 *hh, *hl, *ah, *al, *gh, *gl;
    bf16 *wq, *wk, *wv, *wo, *wg, *wu, *wd, *wh;
    cudaGetSymbolAddress((void**)&x,    g_x);
    cudaGetSymbolAddress((void**)&hh,   g_hh);
    cudaGetSymbolAddress((void**)&hl,   g_hl);
    cudaGetSymbolAddress((void**)&q,    g_q);
    cudaGetSymbolAddress((void**)&k,    g_k);
    cudaGetSymbolAddress((void**)&v,    g_v);
    cudaGetSymbolAddress((void**)&ah,   g_ah);
    cudaGetSymbolAddress((void**)&al,   g_al);
    cudaGetSymbolAddress((void**)&gate, g_gate);
    cudaGetSymbolAddress((void**)&up,   g_up);
    cudaGetSymbolAddress((void**)&gh,   g_gh);
    cudaGetSymbolAddress((void**)&gl,   g_gl);
    cudaGetSymbolAddress((void**)&wq,   g_wq);
    cudaGetSymbolAddress((void**)&wk,   g_wk);
    cudaGetSymbolAddress((void**)&wv,   g_wv);
    cudaGetSymbolAddress((void**)&wo,   g_wo);
    cudaGetSymbolAddress((void**)&wg,   g_wg);
    cudaGetSymbolAddress((void**)&wu,   g_wu);
    cudaGetSymbolAddress((void**)&wd,   g_wd);
    cudaGetSymbolAddress((void**)&wh,   g_wh);

    const long sQsz = (long)Dm * Dm / 128;
    const long sFsz = (long)Dm * FFm / 128;
    const long nD = (long)Lm * Dm * Dm;
    const long nF = (long)Lm * FFm * Dm;
    const long nH = (long)Vv * Dm;

    static bool attr_done = false;
    if (!attr_done) {
        cudaFuncSetAttribute(gemm_kernel,
                             cudaFuncAttributeMaxDynamicSharedMemorySize, GEMM_SMEM);
        cudaFuncSetAttribute(gemm_batch,
                             cudaFuncAttributeMaxDynamicSharedMemorySize, GEMM_SMEM);
        cudaFuncSetAttribute(attn_flash_kernel,
                             cudaFuncAttributeMaxDynamicSharedMemorySize, ATTN_SMEM);
        attr_done = true;
    }

    // ---- single-launch weight conversion ----
    {
        WAll wa;
        const float* srcs[8] = {q_t, k_t, v_t, o_t, gt, ut, dt, head_t};
        bf16* dsts[8]        = {wq,  wk,  wv,  wo,  wg, wu, wd, wh};
        long  szs[8]         = {nD,  nD,  nD,  nD,  nF, nF, nF, nH};
        long c = 0;
        wa.cum[0] = 0;
        for (int i = 0; i < 8; i++) {
            wa.src[i] = srcs[i]; wa.dst[i] = dsts[i];
            c += szs[i] / 4; wa.cum[i + 1] = c;
        }
        w2b_all_kernel<<<(unsigned)((c + 255) / 256), 256>>>(wa);
    }

    embed_kernel<<<Tn, 256>>>(ids, emb_t, emb_s, pos, x);

    dim3 gD(Dm / 128,  Tn / 64);         // 256
    dim3 gQKV(Dm / 128, Tn / 64, 3);     // 768
    dim3 gGU(FFm / 128, Tn / 64, 2);     // 2048
    dim3 gVg(Vv / 128, Tn / 64);         // 8000
    dim3 ga(Sm / 128, Hm, Bm);           // 256 balanced blocks

    for (int l = 0; l < Lm; l++) {
        long oD = (long)l * Dm * Dm;
        long oF = (long)l * FFm * Dm;

        rms_kernel<<<Tn, 256>>>(x, na_w + l * Dm, hh, hl);

        GB3 qkv;
        qkv.w0 = wq + oD; qkv.s0 = q_s + l * sQsz; qkv.y0 = q;
        qkv.w1 = wk + oD; qkv.s1 = k_s + l * sQsz; qkv.y1 = k;
        qkv.w2 = wv + oD; qkv.s2 = v_s + l * sQsz; qkv.y2 = v;
        gemm_batch<<<gQKV, 256, GEMM_SMEM>>>(hh, hl, qkv, Dm, Dm);

        attn_flash_kernel<<<ga, 128, ATTN_SMEM>>>(q, k, v, hh, hl, alpha, l, ah, al);

        gemm_kernel<<<gD, 256, GEMM_SMEM>>>(ah, al, wo + oD, o_s + l * sQsz,
                                            x, x, Dm, Dm);

        rms_kernel<<<Tn, 256>>>(x, nm_w + l * Dm, hh, hl);

        GB3 gu;
        gu.w0 = wg + oF; gu.s0 = gs + l * sFsz; gu.y0 = gate;
        gu.w1 = wu + oF; gu.s1 = us + l * sFsz; gu.y1 = up;
        gu.w2 = gu.w1;   gu.s2 = gu.s1;         gu.y2 = up;
        gemm_batch<<<gGU, 256, GEMM_SMEM>>>(hh, hl, gu, FFm, Dm);

        long n4 = (long)Tn * FFm / 4;
        silu_mul_kernel<<<(unsigned)((n4 + 255) / 256), 256>>>(gate, up, gh, gl, n4);

        gemm_kernel<<<gD, 256, GEMM_SMEM>>>(gh, gl, wd + oF, ds + l * sFsz,
                                            x, x, Dm, FFm);
    }

    rms_kernel<<<Tn, 256>>>(x, nf_w, hh, hl);
    gemm_kernel<<<gVg, 256, GEMM_SMEM>>>(hh, hl, wh, head_s, nullptr,
                                         (float*)d_out, Vv, Dm);
}

// round 17
// speedup vs baseline: 2.3164x; 1.1297x over previous
#include <cuda_runtime.h>
#include <cuda_bf16.h>
#include <math.h>
#include <stdint.h>

#define Tn  2048
#define Dm  1024
#define FFm 4096
#define Vv  32000
#define Bm  2
#define Sm  1024
#define Hm  16
#define Lm  6

typedef __nv_bfloat16 bf16;

// ---------------- scratch (static device globals; no allocation) ------------
__device__ float g_x  [Tn * Dm];
__device__ bf16  g_hh [Tn * Dm];
__device__ bf16  g_hl [Tn * Dm];
__device__ float g_q  [Tn * Dm];
__device__ float g_k  [Tn * Dm];
__device__ float g_v  [Tn * Dm];
__device__ bf16  g_ah [Tn * Dm];
__device__ bf16  g_al [Tn * Dm];
__device__ float g_gate[(long)Tn * FFm];
__device__ float g_up  [(long)Tn * FFm];
__device__ bf16  g_gh [(long)Tn * FFm];
__device__ bf16  g_gl [(long)Tn * FFm];

// bf16 ternary weight caches
__device__ bf16 g_wq[(long)Lm * Dm * Dm];
__device__ bf16 g_wk[(long)Lm * Dm * Dm];
__device__ bf16 g_wv[(long)Lm * Dm * Dm];
__device__ bf16 g_wo[(long)Lm * Dm * Dm];
__device__ bf16 g_wg[(long)Lm * FFm * Dm];
__device__ bf16 g_wu[(long)Lm * FFm * Dm];
__device__ bf16 g_wd[(long)Lm * FFm * Dm];
__device__ bf16 g_wh[(long)Vv * Dm];

__device__ __forceinline__ void split_bf16(float v, bf16& hi, bf16& lo) {
    hi = __float2bfloat16(v);
    lo = __float2bfloat16(v - __bfloat162float(hi));
}
__device__ __forceinline__ void cp_async16(uint32_t dst, const void* src) {
    asm volatile("cp.async.cg.shared.global [%0], [%1], 16;" :: "r"(dst), "l"(src));
}
__device__ __forceinline__ void cp_async4(uint32_t dst, const void* src) {
    asm volatile("cp.async.ca.shared.global [%0], [%1], 4;" :: "r"(dst), "l"(src));
}
__device__ __forceinline__ void cp_commit() {
    asm volatile("cp.async.commit_group;");
}
__device__ __forceinline__ uint32_t smem_u32(const void* p) {
    return (uint32_t)__cvta_generic_to_shared(p);
}
__device__ __forceinline__ void ldsm_x4(uint32_t* r, uint32_t addr) {
    asm volatile("ldmatrix.sync.aligned.m8n8.x4.shared.b16 {%0,%1,%2,%3}, [%4];"
                 : "=r"(r[0]), "=r"(r[1]), "=r"(r[2]), "=r"(r[3]) : "r"(addr));
}
__device__ __forceinline__ void mma_bf16(float* d, const uint32_t* a,
                                         const uint32_t* b) {
    asm volatile(
        "mma.sync.aligned.m16n8k16.row.col.f32.bf16.bf16.f32 "
        "{%0,%1,%2,%3}, {%4,%5,%6,%7}, {%8,%9}, {%0,%1,%2,%3};"
        : "+f"(d[0]), "+f"(d[1]), "+f"(d[2]), "+f"(d[3])
        : "r"(a[0]), "r"(a[1]), "r"(a[2]), "r"(a[3]), "r"(b[0]), "r"(b[1]));
}
__device__ __forceinline__ uint32_t pack_hl(float a, float b, uint32_t& lo) {
    bf16 ah = __float2bfloat16(a), bh = __float2bfloat16(b);
    bf16 al = __float2bfloat16(a - __bfloat162float(ah));
    bf16 bl = __float2bfloat16(b - __bfloat162float(bh));
    __nv_bfloat162 l2(al, bl);
    lo = *(uint32_t*)&l2;
    __nv_bfloat162 h2(ah, bh);
    return *(uint32_t*)&h2;
}

// ---------------- single-launch weight fp32 -> bf16 --------------------------
struct WAll {
    const float* src[8];
    bf16*        dst[8];
    long         cum[9];
};
__global__ void w2b_all_kernel(WAll wa) {
    long i4 = (long)blockIdx.x * blockDim.x + threadIdx.x;
    if (i4 >= wa.cum[8]) return;
    int seg = 0;
    #pragma unroll
    for (int s = 0; s < 7; s++) if (i4 >= wa.cum[s + 1]) seg = s + 1;
    long li = (i4 - wa.cum[seg]) * 4;
    float4 v = *(const float4*)&wa.src[seg][li];
    bf16* d = wa.dst[seg];
    *(__nv_bfloat162*)&d[li]     = __floats2bfloat162_rn(v.x, v.y);
    *(__nv_bfloat162*)&d[li + 2] = __floats2bfloat162_rn(v.z, v.w);
}

// ---------------- embedding + positional ------------------------------------
__global__ void embed_kernel(const int* __restrict__ ids,
                             const float* __restrict__ et,
                             const float* __restrict__ es,
                             const float* __restrict__ pe,
                             float* __restrict__ x) {
    int t  = blockIdx.x;
    int id = ids[t];
    int s  = t % Sm;
    for (int d = threadIdx.x; d < Dm; d += blockDim.x) {
        long wi = (long)id * Dm + d;
        x[(long)t * Dm + d] = et[wi] * es[wi >> 7] + pe[s * Dm + d];
    }
}

// ---------------- RMSNorm -> hi/lo bf16 (register-cached, float4) ------------
__global__ void rms_kernel(const float* __restrict__ X,
                           const float* __restrict__ w,
                           bf16* __restrict__ Yh, bf16* __restrict__ Yl) {
    int t = blockIdx.x, tid = threadIdx.x;
    __shared__ float red[256];
    long base = (long)t * Dm + tid * 4;
    float4 v4 = *(const float4*)&X[base];
    float s = v4.x * v4.x + v4.y * v4.y + v4.z * v4.z + v4.w * v4.w;
    red[tid] = s; __syncthreads();
    for (int o = 128; o > 0; o >>= 1) {
        if (tid < o) red[tid] += red[tid + o];
        __syncthreads();
    }
    float r = rsqrtf(red[0] / Dm + 1e-6f);
    float4 w4 = *(const float4*)&w[tid * 4];
    float y0 = v4.x * r * w4.x, y1 = v4.y * r * w4.y;
    float y2 = v4.z * r * w4.z, y3 = v4.w * r * w4.w;
    bf16 h0, l0, h1, l1, h2, l2, h3, l3;
    split_bf16(y0, h0, l0); split_bf16(y1, h1, l1);
    split_bf16(y2, h2, l2); split_bf16(y3, h3, l3);
    *(__nv_bfloat162*)&Yh[base]     = __nv_bfloat162(h0, h1);
    *(__nv_bfloat162*)&Yh[base + 2] = __nv_bfloat162(h2, h3);
    *(__nv_bfloat162*)&Yl[base]     = __nv_bfloat162(l0, l1);
    *(__nv_bfloat162*)&Yl[base + 2] = __nv_bfloat162(l2, l3);
}

// ---------------- 2-pass GEMM, 64x128 tile, 256 thr, 2 CTA/SM ----------------
#define SAS 72
#define A_ELE (64 * SAS)
#define W_ELE (128 * SAS)
#define STAGE_E (2 * A_ELE + W_ELE)
#define MAXG 32
#define GEMM_SMEM (2 * STAGE_E * (int)sizeof(bf16) + MAXG * 128 * (int)sizeof(float))

__device__ __forceinline__ void gemm_core(const bf16* __restrict__ Xh,
                                          const bf16* __restrict__ Xl,
                                          const bf16* __restrict__ W,
                                          const float* __restrict__ Sc,
                                          const float* __restrict__ res,
                                          float* __restrict__ Y,
                                          int R, int IN, int bm, int bn) {
    extern __shared__ bf16 smp[];
    float* sSc = (float*)(smp + 2 * STAGE_E);

    const int tid  = threadIdx.x;
    const int warp = tid >> 5, lane = tid & 31;
    const int warpM = warp & 1, warpN = warp >> 1;
    const int groups = IN >> 7;
    const int lr = lane >> 2;
    const int lc = (lane & 3) << 1;
    const int lrow  = lane & 15;
    const int lcol8 = (lane >> 4) << 3;

    float master[2][4][4];
    float temp  [2][4][4];
    #pragma unroll
    for (int a = 0; a < 2; a++)
        #pragma unroll
        for (int b = 0; b < 4; b++)
            #pragma unroll
            for (int c = 0; c < 4; c++) { master[a][b][c] = 0.f; temp[a][b][c] = 0.f; }

    const int nIter = IN >> 6;

    auto load_stage = [&](int st, int it) {
        bf16* ah = smp + st * STAGE_E;
        bf16* al = ah + A_ELE;
        bf16* ws = al + A_ELE;
        int k0 = it << 6;
        #pragma unroll
        for (int p = 0; p < 2; p++) {
            int idx = tid + p * 256;
            int m = idx >> 3, c8 = (idx & 7) << 3;
            long gi = (long)(bm + m) * IN + k0 + c8;
            cp_async16(smem_u32(ah + m * SAS + c8), Xh + gi);
            cp_async16(smem_u32(al + m * SAS + c8), Xl + gi);
        }
        #pragma unroll
        for (int p = 0; p < 4; p++) {
            int idx = tid + p * 256;
            int n = idx >> 3, c8 = (idx & 7) << 3;
            cp_async16(smem_u32(ws + n * SAS + c8), W + (long)(bn + n) * IN + k0 + c8);
        }
    };

    load_stage(0, 0);
    for (int idx = tid; idx < groups * 128; idx += 256) {
        int rl = idx & 127, g = idx >> 7;
        cp_async4(smem_u32(sSc + idx), Sc + (long)(bn + rl) * groups + g);
    }
    cp_commit();

    for (int it = 0; it < nIter; it++) {
        if (it + 1 < nIter) {
            load_stage((it + 1) & 1, it + 1);
            cp_commit();
            asm volatile("cp.async.wait_group 1;");
        } else {
            asm volatile("cp.async.wait_group 0;");
        }
        __syncthreads();

        const int st = it & 1;
        const bf16* ah = smp + st * STAGE_E;
        const bf16* al = ah + A_ELE;
        const bf16* ws = al + A_ELE;

        #pragma unroll
        for (int ks = 0; ks < 4; ks++) {
            const int kb = ks * 16;
            uint32_t fah[2][4], fal[2][4], fb[4][2];
            #pragma unroll
            for (int mt = 0; mt < 2; mt++) {
                int m0 = warpM * 32 + mt * 16;
                ldsm_x4(fah[mt], smem_u32(ah + (m0 + lrow) * SAS + kb + lcol8));
                ldsm_x4(fal[mt], smem_u32(al + (m0 + lrow) * SAS + kb + lcol8));
            }
            #pragma unroll
            for (int np = 0; np < 2; np++) {
                int n0 = warpN * 32 + np * 16;
                uint32_t q[4];
                ldsm_x4(q, smem_u32(ws + (n0 + lrow) * SAS + kb + lcol8));
                fb[np * 2][0] = q[0];     fb[np * 2][1] = q[2];
                fb[np * 2 + 1][0] = q[1]; fb[np * 2 + 1][1] = q[3];
            }
            #pragma unroll
            for (int mt = 0; mt < 2; mt++)
                #pragma unroll
                for (int nt = 0; nt < 4; nt++) {
                    mma_bf16(temp[mt][nt], fah[mt], fb[nt]);
                    mma_bf16(temp[mt][nt], fal[mt], fb[nt]);
                }
        }

        if (it & 1) {
            int g = it >> 1;
            #pragma unroll
            for (int nt = 0; nt < 4; nt++) {
                int rl = warpN * 32 + nt * 8 + lc;
                float s0 = sSc[g * 128 + rl];
                float s1 = sSc[g * 128 + rl + 1];
                #pragma unroll
                for (int mt = 0; mt < 2; mt++) {
                    master[mt][nt][0] += s0 * temp[mt][nt][0];
                    master[mt][nt][1] += s1 * temp[mt][nt][1];
                    master[mt][nt][2] += s0 * temp[mt][nt][2];
                    master[mt][nt][3] += s1 * temp[mt][nt][3];
                    temp[mt][nt][0] = 0.f; temp[mt][nt][1] = 0.f;
                    temp[mt][nt][2] = 0.f; temp[mt][nt][3] = 0.f;
                }
            }
        }
        __syncthreads();
    }

    #pragma unroll
    for (int mt = 0; mt < 2; mt++) {
        int m0 = bm + warpM * 32 + mt * 16 + lr;
        #pragma unroll
        for (int nt = 0; nt < 4; nt++) {
            int r0 = bn + warpN * 32 + nt * 8 + lc;
            float2 v0 = make_float2(master[mt][nt][0], master[mt][nt][1]);
            float2 v1 = make_float2(master[mt][nt][2], master[mt][nt][3]);
            if (res) {
                float2 p0 = *(const float2*)&res[(long)m0 * R + r0];
                float2 p1 = *(const float2*)&res[(long)(m0 + 8) * R + r0];
                v0.x += p0.x; v0.y += p0.y;
                v1.x += p1.x; v1.y += p1.y;
            }
            *(float2*)&Y[(long)m0 * R + r0]       = v0;
            *(float2*)&Y[(long)(m0 + 8) * R + r0] = v1;
        }
    }
}

__global__ void __launch_bounds__(256, 2)
gemm_kernel(const bf16* __restrict__ Xh, const bf16* __restrict__ Xl,
            const bf16* __restrict__ W, const float* __restrict__ Sc,
            const float* __restrict__ res, float* __restrict__ Y,
            int R, int IN) {
    gemm_core(Xh, Xl, W, Sc, res, Y, R, IN, blockIdx.y * 64, blockIdx.x * 128);
}

struct GB3 {
    const bf16 *w0, *w1, *w2;
    const float *s0, *s1, *s2;
    float *y0, *y1, *y2;
};
__global__ void __launch_bounds__(256, 2)
gemm_batch(const bf16* __restrict__ Xh, const bf16* __restrict__ Xl,
           GB3 gb, int R, int IN) {
    int z = blockIdx.z;
    const bf16*  W  = (z == 0) ? gb.w0 : (z == 1) ? gb.w1 : gb.w2;
    const float* Sc = (z == 0) ? gb.s0 : (z == 1) ? gb.s1 : gb.s2;
    float*       Y  = (z == 0) ? gb.y0 : (z == 1) ? gb.y1 : gb.y2;
    gemm_core(Xh, Xl, W, Sc, nullptr, Y, R, IN, blockIdx.y * 64, blockIdx.x * 128);
}

// ---------------- FA2 tensor-core flash attention -----------------------------
// 128 threads, 4 warps, q-tile 64 (warp = 16 rows), k-tiles 64.
// Q,K,P,V in hi/lo bf16 (lo*lo dropped, err ~2^-18). V stored transposed.
#define AS 72
#define ATILE (64 * AS)
#define ATTN_SMEM (6 * ATILE * (int)sizeof(bf16))   // 55296

__global__ void __launch_bounds__(128)
attn_flash_kernel(const float* __restrict__ Q,
                  const float* __restrict__ K,
                  const float* __restrict__ V,
                  const bf16* __restrict__ Hh,
                  const bf16* __restrict__ Hl,
                  const float* __restrict__ alpha,
                  int layer,
                  bf16* __restrict__ Oh, bf16* __restrict__ Ol) {
    extern __shared__ bf16 asm_[];
    bf16* sQh = asm_;
    bf16* sQl = sQh + ATILE;
    bf16* sKh = sQl + ATILE;
    bf16* sKl = sKh + ATILE;
    bf16* sVh = sKl + ATILE;   // transposed: [d][key]
    bf16* sVl = sVh + ATILE;

    const int nQT = Sm / 64;
    const int h = blockIdx.y, b = blockIdx.z;
    const int tid = threadIdx.x, w = tid >> 5, lane = tid & 31;
    const int lr = lane >> 2;            // 0..7
    const int lc = (lane & 3) << 1;      // 0,2,4,6
    const int lrow  = lane & 15;
    const int lcol8 = (lane >> 4) << 3;
    const int hoff = h * 64;

    #pragma unroll
    for (int pass = 0; pass < 2; pass++) {
        const int qt = (pass == 0) ? blockIdx.x : (nQT - 1 - blockIdx.x);
        const long tok0 = (long)b * Sm + qt * 64;

        __syncthreads();
        for (int i = tid; i < 4096; i += 128) {
            int row = i >> 6, d = i & 63;
            float qv = Q[(tok0 + row) * Dm + hoff + d];
            bf16 hi, lo; split_bf16(qv, hi, lo);
            sQh[row * AS + d] = hi; sQl[row * AS + d] = lo;
        }

        float m0 = -1e30f, m1 = -1e30f, l0 = 0.f, l1 = 0.f;
        float acc[8][4];
        #pragma unroll
        for (int dt = 0; dt < 8; dt++)
            #pragma unroll
            for (int j = 0; j < 4; j++) acc[dt][j] = 0.f;

        const int nkt = qt + 1;
        for (int kt = 0; kt < nkt; kt++) {
            __syncthreads();
            long kbase = (long)b * Sm + kt * 64;
            for (int i = tid; i < 4096; i += 128) {
                int key = i >> 6, d = i & 63;
                float kf = K[(kbase + key) * Dm + hoff + d];
                bf16 hi, lo; split_bf16(kf, hi, lo);
                sKh[key * AS + d] = hi; sKl[key * AS + d] = lo;
                float vf = V[(kbase + key) * Dm + hoff + d];
                split_bf16(vf, hi, lo);
                sVh[d * AS + key] = hi; sVl[d * AS + key] = lo;
            }
            __syncthreads();

            // ---- QK^T via mma (3 passes)
            float sc[8][4];
            #pragma unroll
            for (int nt = 0; nt < 8; nt++)
                #pragma unroll
                for (int j = 0; j < 4; j++) sc[nt][j] = 0.f;
            #pragma unroll
            for (int ks = 0; ks < 4; ks++) {
                const int kb = ks * 16;
                uint32_t qh[4], ql[4], kh[8][2], kl[8][2];
                ldsm_x4(qh, smem_u32(sQh + (w * 16 + lrow) * AS + kb + lcol8));
                ldsm_x4(ql, smem_u32(sQl + (w * 16 + lrow) * AS + kb + lcol8));
                #pragma unroll
                for (int np = 0; np < 4; np++) {
                    uint32_t t4[4];
                    ldsm_x4(t4, smem_u32(sKh + (np * 16 + lrow) * AS + kb + lcol8));
                    kh[np * 2][0] = t4[0];     kh[np * 2][1] = t4[2];
                    kh[np * 2 + 1][0] = t4[1]; kh[np * 2 + 1][1] = t4[3];
                    ldsm_x4(t4, smem_u32(sKl + (np * 16 + lrow) * AS + kb + lcol8));
                    kl[np * 2][0] = t4[0];     kl[np * 2][1] = t4[2];
                    kl[np * 2 + 1][0] = t4[1]; kl[np * 2 + 1][1] = t4[3];
                }
                #pragma unroll
                for (int nt = 0; nt < 8; nt++) {
                    mma_bf16(sc[nt], qh, kh[nt]);
                    mma_bf16(sc[nt], ql, kh[nt]);
                    mma_bf16(sc[nt], qh, kl[nt]);
                }
            }

            // ---- scale + causal mask (fragment layout)
            const int qg0 = qt * 64 + w * 16 + lr;
            const int qg1 = qg0 + 8;
            const bool diag = (kt == qt);
            #pragma unroll
            for (int nt = 0; nt < 8; nt++) {
                int k0g = kt * 64 + nt * 8 + lc;
                sc[nt][0] *= 0.125f; sc[nt][1] *= 0.125f;
                sc[nt][2] *= 0.125f; sc[nt][3] *= 0.125f;
                if (diag) {
                    if (k0g     > qg0) sc[nt][0] = -1e30f;
                    if (k0g + 1 > qg0) sc[nt][1] = -1e30f;
                    if (k0g     > qg1) sc[nt][2] = -1e30f;
                    if (k0g + 1 > qg1) sc[nt][3] = -1e30f;
                }
            }

            // ---- online softmax (rows lr / lr+8; quad reduce)
            float mx0 = -1e30f, mx1 = -1e30f;
            #pragma unroll
            for (int nt = 0; nt < 8; nt++) {
                mx0 = fmaxf(mx0, fmaxf(sc[nt][0], sc[nt][1]));
                mx1 = fmaxf(mx1, fmaxf(sc[nt][2], sc[nt][3]));
            }
            #pragma unroll
            for (int o = 1; o < 4; o <<= 1) {
                mx0 = fmaxf(mx0, __shfl_xor_sync(0xffffffffu, mx0, o));
                mx1 = fmaxf(mx1, __shfl_xor_sync(0xffffffffu, mx1, o));
            }
            float mn0 = fmaxf(mx0, m0), mn1 = fmaxf(mx1, m1);
            float fac0 = __expf(m0 - mn0), fac1 = __expf(m1 - mn1);
            m0 = mn0; m1 = mn1;
            float ls0 = 0.f, ls1 = 0.f;
            #pragma unroll
            for (int nt = 0; nt < 8; nt++) {
                sc[nt][0] = __expf(sc[nt][0] - mn0);
                sc[nt][1] = __expf(sc[nt][1] - mn0);
                sc[nt][2] = __expf(sc[nt][2] - mn1);
                sc[nt][3] = __expf(sc[nt][3] - mn1);
                ls0 += sc[nt][0] + sc[nt][1];
                ls1 += sc[nt][2] + sc[nt][3];
            }
            #pragma unroll
            for (int o = 1; o < 4; o <<= 1) {
                ls0 += __shfl_xor_sync(0xffffffffu, ls0, o);
                ls1 += __shfl_xor_sync(0xffffffffu, ls1, o);
            }
            l0 = l0 * fac0 + ls0;
            l1 = l1 * fac1 + ls1;
            #pragma unroll
            for (int dt = 0; dt < 8; dt++) {
                acc[dt][0] *= fac0; acc[dt][1] *= fac0;
                acc[dt][2] *= fac1; acc[dt][3] *= fac1;
            }

            // ---- pack P into A-fragments (hi/lo)
            uint32_t ph[4][4], pl[4][4];
            #pragma unroll
            for (int s = 0; s < 4; s++) {
                ph[s][0] = pack_hl(sc[2 * s][0],     sc[2 * s][1],     pl[s][0]);
                ph[s][1] = pack_hl(sc[2 * s][2],     sc[2 * s][3],     pl[s][1]);
                ph[s][2] = pack_hl(sc[2 * s + 1][0], sc[2 * s + 1][1], pl[s][2]);
                ph[s][3] = pack_hl(sc[2 * s + 1][2], sc[2 * s + 1][3], pl[s][3]);
            }

            // ---- PV via mma (3 passes), B = V^T[d][key]
            #pragma unroll
            for (int ks = 0; ks < 4; ks++) {
                const int kb = ks * 16;
                uint32_t vh[8][2], vl[8][2];
                #pragma unroll
                for (int nd = 0; nd < 4; nd++) {
                    uint32_t t4[4];
                    ldsm_x4(t4, smem_u32(sVh + (nd * 16 + lrow) * AS + kb + lcol8));
                    vh[nd * 2][0] = t4[0];     vh[nd * 2][1] = t4[2];
                    vh[nd * 2 + 1][0] = t4[1]; vh[nd * 2 + 1][1] = t4[3];
                    ldsm_x4(t4, smem_u32(sVl + (nd * 16 + lrow) * AS + kb + lcol8));
                    vl[nd * 2][0] = t4[0];     vl[nd * 2][1] = t4[2];
                    vl[nd * 2 + 1][0] = t4[1]; vl[nd * 2 + 1][1] = t4[3];
                }
                #pragma unroll
                for (int dt = 0; dt < 8; dt++) {
                    mma_bf16(acc[dt], ph[ks], vh[dt]);
                    mma_bf16(acc[dt], pl[ks], vh[dt]);
                    mma_bf16(acc[dt], ph[ks], vl[dt]);
                }
            }
        }

        // ---- epilogue: /l, + alpha*h, hi/lo bf16 stores
        float a = alpha[layer * Hm + h];
        float inv0 = 1.f / l0, inv1 = 1.f / l1;
        #pragma unroll
        for (int dt = 0; dt < 8; dt++) {
            int d0 = hoff + dt * 8 + lc;
            long r0 = (tok0 + w * 16 + lr) * Dm + d0;
            long r1 = r0 + 8 * Dm;
            __nv_bfloat162 hh0 = *(const __nv_bfloat162*)&Hh[r0];
            __nv_bfloat162 hl0 = *(const __nv_bfloat162*)&Hl[r0];
            __nv_bfloat162 hh1 = *(const __nv_bfloat162*)&Hh[r1];
            __nv_bfloat162 hl1 = *(const __nv_bfloat162*)&Hl[r1];
            float v00 = acc[dt][0] * inv0 +
                        a * (__bfloat162float(hh0.x) + __bfloat162float(hl0.x));
            float v01 = acc[dt][1] * inv0 +
                        a * (__bfloat162float(hh0.y) + __bfloat162float(hl0.y));
            float v10 = acc[dt][2] * inv1 +
                        a * (__bfloat162float(hh1.x) + __bfloat162float(hl1.x));
            float v11 = acc[dt][3] * inv1 +
                        a * (__bfloat162float(hh1.y) + __bfloat162float(hl1.y));
            uint32_t o0l, o1l;
            uint32_t o0h = pack_hl(v00, v01, o0l);
            uint32_t o1h = pack_hl(v10, v11, o1l);
            *(uint32_t*)&Oh[r0] = o0h; *(uint32_t*)&Ol[r0] = o0l;
            *(uint32_t*)&Oh[r1] = o1h; *(uint32_t*)&Ol[r1] = o1l;
        }
    }
}

// ---------------- SiLU(gate) * up -> hi/lo bf16 (float4, __expf) -------------
__global__ void silu_mul_kernel(const float* __restrict__ g,
                                const float* __restrict__ u,
                                bf16* __restrict__ Yh, bf16* __restrict__ Yl,
                                long n4) {
    long i = ((long)blockIdx.x * blockDim.x + threadIdx.x);
    if (i < n4) {
        long b = i * 4;
        float4 gv = *(const float4*)&g[b];
        float4 uv = *(const float4*)&u[b];
        float v0 = (gv.x / (1.f + __expf(-gv.x))) * uv.x;
        float v1 = (gv.y / (1.f + __expf(-gv.y))) * uv.y;
        float v2 = (gv.z / (1.f + __expf(-gv.z))) * uv.z;
        float v3 = (gv.w / (1.f + __expf(-gv.w))) * uv.w;
        bf16 h0, l0, h1, l1, h2, l2, h3, l3;
        split_bf16(v0, h0, l0); split_bf16(v1, h1, l1);
        split_bf16(v2, h2, l2); split_bf16(v3, h3, l3);
        *(__nv_bfloat162*)&Yh[b]     = __nv_bfloat162(h0, h1);
        *(__nv_bfloat162*)&Yh[b + 2] = __nv_bfloat162(h2, h3);
        *(__nv_bfloat162*)&Yl[b]     = __nv_bfloat162(l0, l1);
        *(__nv_bfloat162*)&Yl[b + 2] = __nv_bfloat162(l2, l3);
    }
}

// =============================================================================
extern "C" void kernel_launch(void* const* d_in, const int* in_sizes, int n_in,
                              void* d_out, int out_size) {
    const int*   ids    = (const int*)  d_in[0];
    const float* emb_t  = (const float*)d_in[1];
    const float* emb_s  = (const float*)d_in[2];
    const float* pos    = (const float*)d_in[3];
    const float* q_t    = (const float*)d_in[4];
    const float* q_s    = (const float*)d_in[5];
    const float* k_t    = (const float*)d_in[6];
    const float* k_s    = (const float*)d_in[7];
    const float* v_t    = (const float*)d_in[8];
    const float* v_s    = (const float*)d_in[9];
    const float* o_t    = (const float*)d_in[10];
    const float* o_s    = (const float*)d_in[11];
    const float* gt     = (const float*)d_in[12];
    const float* gs     = (const float*)d_in[13];
    const float* ut     = (const float*)d_in[14];
    const float* us     = (const float*)d_in[15];
    const float* dt     = (const float*)d_in[16];
    const float* ds     = (const float*)d_in[17];
    const float* alpha  = (const float*)d_in[18];
    const float* na_w   = (const float*)d_in[19];
    const float* nm_w   = (const float*)d_in[20];
    const float* nf_w   = (const float*)d_in[21];
    const float* head_t = (const float*)d_in[22];
    const float* head_s = (const float*)d_in[23];

    float *x, *q, *k, *v, *gate, *up;
    bf16 *hh, *hl, *ah, *al, *gh, *gl;
    bf16 *wq, *wk, *wv, *wo, *wg, *wu, *wd, *wh;
    cudaGetSymbolAddress((void**)&x,    g_x);
    cudaGetSymbolAddress((void**)&hh,   g_hh);
    cudaGetSymbolAddress((void**)&hl,   g_hl);
    cudaGetSymbolAddress((void**)&q,    g_q);
    cudaGetSymbolAddress((void**)&k,    g_k);
    cudaGetSymbolAddress((void**)&v,    g_v);
    cudaGetSymbolAddress((void**)&ah,   g_ah);
    cudaGetSymbolAddress((void**)&al,   g_al);
    cudaGetSymbolAddress((void**)&gate, g_gate);
    cudaGetSymbolAddress((void**)&up,   g_up);
    cudaGetSymbolAddress((void**)&gh,   g_gh);
    cudaGetSymbolAddress((void**)&gl,   g_gl);
    cudaGetSymbolAddress((void**)&wq,   g_wq);
    cudaGetSymbolAddress((void**)&wk,   g_wk);
    cudaGetSymbolAddress((void**)&wv,   g_wv);
    cudaGetSymbolAddress((void**)&wo,   g_wo);
    cudaGetSymbolAddress((void**)&wg,   g_wg);
    cudaGetSymbolAddress((void**)&wu,   g_wu);
    cudaGetSymbolAddress((void**)&wd,   g_wd);
    cudaGetSymbolAddress((void**)&wh,   g_wh);

    const long sQsz = (long)Dm * Dm / 128;
    const long sFsz = (long)Dm * FFm / 128;
    const long nD = (long)Lm * Dm * Dm;
    const long nF = (long)Lm * FFm * Dm;
    const long nH = (long)Vv * Dm;

    static bool attr_done = false;
    if (!attr_done) {
        cudaFuncSetAttribute(gemm_kernel,
                             cudaFuncAttributeMaxDynamicSharedMemorySize, GEMM_SMEM);
        cudaFuncSetAttribute(gemm_batch,
                             cudaFuncAttributeMaxDynamicSharedMemorySize, GEMM_SMEM);
        cudaFuncSetAttribute(attn_flash_kernel,
                             cudaFuncAttributeMaxDynamicSharedMemorySize, ATTN_SMEM);
        attr_done = true;
    }

    // ---- single-launch weight conversion ----
    {
        WAll wa;
        const float* srcs[8] = {q_t, k_t, v_t, o_t, gt, ut, dt, head_t};
        bf16* dsts[8]        = {wq,  wk,  wv,  wo,  wg, wu, wd, wh};
        long  szs[8]         = {nD,  nD,  nD,  nD,  nF, nF, nF, nH};
        long c = 0;
        wa.cum[0] = 0;
        for (int i = 0; i < 8; i++) {
            wa.src[i] = srcs[i]; wa.dst[i] = dsts[i];
            c += szs[i] / 4; wa.cum[i + 1] = c;
        }
        w2b_all_kernel<<<(unsigned)((c + 255) / 256), 256>>>(wa);
    }

    embed_kernel<<<Tn, 256>>>(ids, emb_t, emb_s, pos, x);

    dim3 gD(Dm / 128,  Tn / 64);         // 256
    dim3 gQKV(Dm / 128, Tn / 64, 3);     // 768
    dim3 gGU(FFm / 128, Tn / 64, 2);     // 2048
    dim3 gVg(Vv / 128, Tn / 64);         // 8000
    dim3 ga(Sm / 128, Hm, Bm);           // 256 balanced blocks

    for (int l = 0; l < Lm; l++) {
        long oD = (long)l * Dm * Dm;
        long oF = (long)l * FFm * Dm;

        rms_kernel<<<Tn, 256>>>(x, na_w + l * Dm, hh, hl);

        GB3 qkv;
        qkv.w0 = wq + oD; qkv.s0 = q_s + l * sQsz; qkv.y0 = q;
        qkv.w1 = wk + oD; qkv.s1 = k_s + l * sQsz; qkv.y1 = k;
        qkv.w2 = wv + oD; qkv.s2 = v_s + l * sQsz; qkv.y2 = v;
        gemm_batch<<<gQKV, 256, GEMM_SMEM>>>(hh, hl, qkv, Dm, Dm);

        attn_flash_kernel<<<ga, 128, ATTN_SMEM>>>(q, k, v, hh, hl, alpha, l, ah, al);

        gemm_kernel<<<gD, 256, GEMM_SMEM>>>(ah, al, wo + oD, o_s + l * sQsz,
                                            x, x, Dm, Dm);

        rms_kernel<<<Tn, 256>>>(x, nm_w + l * Dm, hh, hl);

        GB3 gu;
        gu.w0 = wg + oF; gu.s0 = gs + l * sFsz; gu.y0 = gate;
        gu.w1 = wu + oF; gu.s1 = us + l * sFsz; gu.y1 = up;
        gu.w2 = gu.w1;   gu.s2 = gu.s1;         gu.y2 = up;
        gemm_batch<<<gGU, 256, GEMM_SMEM>>>(hh, hl, gu, FFm, Dm);

        long n4 = (long)Tn * FFm / 4;
        silu_mul_kernel<<<(unsigned)((n4 + 255) / 256), 256>>>(gate, up, gh, gl, n4);

        gemm_kernel<<<gD, 256, GEMM_SMEM>>>(gh, gl, wd + oF, ds + l * sFsz,
                                            x, x, Dm, FFm);
    }

    rms_kernel<<<Tn, 256>>>(x, nf_w, hh, hl);
    gemm_kernel<<<gVg, 256, GEMM_SMEM>>>(hh, hl, wh, head_s, nullptr,
                                         (float*)d_out, Vv, Dm);
}